// round 10
// baseline (speedup 1.0000x reference)
#include <cuda_runtime.h>
#include <cuda_bf16.h>
#include <cuda_fp16.h>
#include <math.h>
#include <stdint.h>

#define D_DIM 256
#define O_DIM 32
#define NMAX 50000
#define EMAX 800000

// ---------------- scratch (static device globals; no runtime allocation) ---
__device__ float g_B[(size_t)NMAX * D_DIM];   // h1 = A@W+b
__device__ float g_C[(size_t)NMAX * D_DIM];   // nb  (fused weights)
__device__ __half g_Yh[(size_t)NMAX * D_DIM]; // dinv * nb (fp16, gather source)
__device__ __nv_bfloat16 g_Ah[(size_t)NMAX * D_DIM];  // GEMM input hi
__device__ __nv_bfloat16 g_Al[(size_t)NMAX * D_DIM];  // GEMM input lo
__device__ __nv_bfloat16 g_Wh[2][512 * 256];  // packed weights [n][k] hi
__device__ __nv_bfloat16 g_Wl[2][512 * 256];  // packed weights [n][k] lo
__device__ float g_biasC[2][512];
__device__ float g_Wf[2][256 * 256];          // W @ Wn per layer
__device__ float g_bf[2][256];                // b @ Wn + bn per layer
__device__ float g_dinv[NMAX];
__device__ int   g_cnt[NMAX];
__device__ int   g_rowstart[NMAX];
__device__ int   g_cursor[NMAX];
__device__ int   g_colidx[EMAX];
__device__ int   g_base;                      // global slot cursor

// ================= helpers =================================================
__device__ __forceinline__ uint32_t smem_u32(const void* p) {
    uint32_t a;
    asm("{ .reg .u64 t; cvta.to.shared.u64 t, %1; cvt.u32.u64 %0, t; }"
        : "=r"(a) : "l"(p));
    return a;
}
__device__ __forceinline__ void ldsm_x4(uint32_t* r, uint32_t addr) {
    asm volatile("ldmatrix.sync.aligned.m8n8.x4.shared.b16 {%0,%1,%2,%3}, [%4];"
                 : "=r"(r[0]), "=r"(r[1]), "=r"(r[2]), "=r"(r[3]) : "r"(addr));
}
__device__ __forceinline__ void mma_bf16(float* c, const uint32_t* a,
                                         uint32_t b0, uint32_t b1) {
    asm volatile(
        "mma.sync.aligned.m16n8k16.row.col.f32.bf16.bf16.f32 "
        "{%0,%1,%2,%3}, {%4,%5,%6,%7}, {%8,%9}, {%0,%1,%2,%3};"
        : "+f"(c[0]), "+f"(c[1]), "+f"(c[2]), "+f"(c[3])
        : "r"(a[0]), "r"(a[1]), "r"(a[2]), "r"(a[3]), "r"(b0), "r"(b1));
}
__device__ __forceinline__ void cp16(uint32_t s, const void* g, bool p) {
    asm volatile("cp.async.cg.shared.global [%0], [%1], 16, %2;"
                 :: "r"(s), "l"(g), "r"(p ? 16 : 0));
}
#define CP_COMMIT() asm volatile("cp.async.commit_group;" ::: "memory")
#define CP_WAIT(n)  asm volatile("cp.async.wait_group %0;" :: "n"(n) : "memory")
#define SW128(off) ((off) ^ (((off) >> 3) & 0x70))

// ---------------- CSR build (scan-free) ------------------------------------
__global__ void count_edges_kernel(const int* __restrict__ row, int e) {
    int i = blockIdx.x * blockDim.x + threadIdx.x;
    if (i < e) atomicAdd(&g_cnt[row[i]], 1);
}
__global__ void offsets_kernel(int n) {
    int i = blockIdx.x * blockDim.x + threadIdx.x;
    int lane = threadIdx.x & 31;
    int c = (i < n) ? g_cnt[i] : 0;
    int incl = c;
    #pragma unroll
    for (int o = 1; o < 32; o <<= 1) {
        int v = __shfl_up_sync(0xffffffffu, incl, o);
        if (lane >= o) incl += v;
    }
    int total = __shfl_sync(0xffffffffu, incl, 31);
    int base = 0;
    if (lane == 31 && total > 0) base = atomicAdd(&g_base, total);
    base = __shfl_sync(0xffffffffu, base, 31);
    if (i < n) {
        int start = base + incl - c;
        g_rowstart[i] = start;
        g_cursor[i]   = start;
        g_dinv[i]     = rsqrtf((float)(c + 1));
    }
}
__global__ void fill_csr_kernel(const int* __restrict__ row,
                                const int* __restrict__ col, int e) {
    int i = blockIdx.x * blockDim.x + threadIdx.x;
    if (i < e) {
        int p = atomicAdd(&g_cursor[row[i]], 1);
        g_colidx[p] = col[i];
    }
}

// ---------------- weight prep ---------------------------------------------
__global__ void fuse_wb_kernel(const float* __restrict__ W,
                               const float* __restrict__ Wn,
                               const float* __restrict__ b,
                               const float* __restrict__ bn, int layer) {
    int n = threadIdx.x;
    int kb = blockIdx.x;
    if (kb < 256) {
        const float* wrow = W + kb * 256;
        float acc = 0.0f;
        #pragma unroll 8
        for (int j = 0; j < 256; j++)
            acc = fmaf(__ldg(wrow + j), Wn[j * 256 + n], acc);
        g_Wf[layer][kb * 256 + n] = acc;
    } else {
        float acc = bn[n];
        #pragma unroll 8
        for (int j = 0; j < 256; j++)
            acc = fmaf(__ldg(b + j), Wn[j * 256 + n], acc);
        g_bf[layer][n] = acc;
    }
}
__global__ void pack_w_kernel(const float* __restrict__ W,
                              const float* __restrict__ b, int layer) {
    __shared__ float s[32][33];
    int k0 = blockIdx.x * 32, n0 = blockIdx.y * 32;
    int tx = threadIdx.x, ty = threadIdx.y;
    #pragma unroll
    for (int i = 0; i < 4; i++) {
        int k = k0 + ty + i * 8;
        float v = (n0 < 256) ? W[k * 256 + n0 + tx]
                             : g_Wf[layer][k * 256 + (n0 - 256) + tx];
        s[ty + i * 8][tx] = v;
    }
    __syncthreads();
    #pragma unroll
    for (int i = 0; i < 4; i++) {
        int n = n0 + ty + i * 8;
        float w = s[tx][ty + i * 8];
        __nv_bfloat16 hi = __float2bfloat16(w);
        g_Wh[layer][n * 256 + k0 + tx] = hi;
        g_Wl[layer][n * 256 + k0 + tx] = __float2bfloat16(w - __bfloat162float(hi));
    }
    if (blockIdx.x == 0 && tx == 0) {
        #pragma unroll
        for (int i = 0; i < 4; i++) {
            int n = n0 + ty + i * 8;
            g_biasC[layer][n] = (n < 256) ? b[n] : g_bf[layer][n - 256];
        }
    }
}
__global__ void split_kernel(const float* __restrict__ x, int total4) {
    int i = blockIdx.x * blockDim.x + threadIdx.x;
    if (i < total4) {
        float4 v = reinterpret_cast<const float4*>(x)[i];
        __nv_bfloat16 h0 = __float2bfloat16(v.x), h1 = __float2bfloat16(v.y);
        __nv_bfloat16 h2 = __float2bfloat16(v.z), h3 = __float2bfloat16(v.w);
        __nv_bfloat162 hA, hB, lA, lB;
        hA.x = h0; hA.y = h1; hB.x = h2; hB.y = h3;
        lA.x = __float2bfloat16(v.x - __bfloat162float(h0));
        lA.y = __float2bfloat16(v.y - __bfloat162float(h1));
        lB.x = __float2bfloat16(v.z - __bfloat162float(h2));
        lB.y = __float2bfloat16(v.w - __bfloat162float(h3));
        reinterpret_cast<__nv_bfloat162*>(g_Ah)[i * 2]     = hA;
        reinterpret_cast<__nv_bfloat162*>(g_Ah)[i * 2 + 1] = hB;
        reinterpret_cast<__nv_bfloat162*>(g_Al)[i * 2]     = lA;
        reinterpret_cast<__nv_bfloat162*>(g_Al)[i * 2 + 1] = lB;
    }
}

// ---------------- HMMA GEMM: [B|C] = A @ Wcomb, split-bf16 x3 --------------
// R4 mainloop (profiled 198us). Epilogue: B half -> Bout; C half -> Cout fp32
// + Yh = dinv*C in fp16 (halves the agg gather traffic).
#define STAGE_BYTES 65536
__global__ __launch_bounds__(256)
void hmma_gemm_kernel(const __nv_bfloat16* __restrict__ Ah,
                      const __nv_bfloat16* __restrict__ Al,
                      const __nv_bfloat16* __restrict__ Wh,
                      const __nv_bfloat16* __restrict__ Wl,
                      const float* __restrict__ bias,
                      float* __restrict__ Bout, float* __restrict__ Cout,
                      __half* __restrict__ Yh, const float* __restrict__ dinv,
                      int M)
{
    extern __shared__ char dsm_raw[];
    uint32_t dynu = smem_u32(dsm_raw);
    uint32_t pad = ((dynu + 127) & ~127u) - dynu;
    uint32_t sb = dynu + pad;
    const uint32_t OFF_AH = 0, OFF_AL = 16384, OFF_BH = 32768, OFF_BL = 49152;

    int tid  = threadIdx.x;
    int warp = tid >> 5, lane = tid & 31;
    int brow = blockIdx.x * 128;
    int ncb  = blockIdx.y * 128;
    int wm   = (warp >> 2) * 64;
    int wn   = (warp & 3) * 32;

    int lr  = tid >> 3;
    int lc8 = tid & 7;

    float acc[4][4][4];
    #pragma unroll
    for (int mi = 0; mi < 4; mi++)
        #pragma unroll
        for (int ni = 0; ni < 4; ni++)
            #pragma unroll
            for (int q = 0; q < 4; q++) acc[mi][ni][q] = 0.0f;

    auto load_chunk = [&](int chunk, int stage) {
        int k0 = chunk * 64;
        uint32_t sbase = sb + stage * STAGE_BYTES;
        #pragma unroll
        for (int l = 0; l < 4; l++) {
            int r = lr + l * 32;
            int gr = brow + r;
            bool p = gr < M;
            uint32_t sw = SW128((uint32_t)(r * 128 + lc8 * 16));
            size_t oa = (size_t)(p ? gr : 0) * 256 + k0 + lc8 * 8;
            cp16(sbase + OFF_AH + sw, Ah + oa, p);
            cp16(sbase + OFF_AL + sw, Al + oa, p);
            size_t ow = (size_t)(ncb + r) * 256 + k0 + lc8 * 8;
            cp16(sbase + OFF_BH + sw, Wh + ow, true);
            cp16(sbase + OFF_BL + sw, Wl + ow, true);
        }
        CP_COMMIT();
    };

    load_chunk(0, 0);

    for (int chunk = 0; chunk < 4; chunk++) {
        int stage = chunk & 1;
        if (chunk < 3) { load_chunk(chunk + 1, stage ^ 1); CP_WAIT(1); }
        else           { CP_WAIT(0); }
        __syncthreads();

        uint32_t sbase = sb + stage * STAGE_BYTES;
        #pragma unroll
        for (int ks = 0; ks < 4; ks++) {
            uint32_t kb   = (uint32_t)(ks * 32 + ((lane >> 4) & 1) * 16);
            uint32_t kswz = kb ^ ((uint32_t)(lane & 7) << 4);
            uint32_t rsub = (uint32_t)((lane & 7) + ((lane >> 3) & 1) * 8);

            uint32_t adA = sbase + (wm + rsub) * 128 + kswz;
            uint32_t adB = sbase + (wn + rsub) * 128 + kswz;

            uint32_t a[4][4];                    // reused: hi then lo
            uint32_t bh[2][4], bl[2][4];
            #pragma unroll
            for (int mi = 0; mi < 4; mi++)
                ldsm_x4(a[mi], adA + OFF_AH + mi * 2048);
            #pragma unroll
            for (int nj = 0; nj < 2; nj++) {
                ldsm_x4(bh[nj], adB + OFF_BH + nj * 2048);
                ldsm_x4(bl[nj], adB + OFF_BL + nj * 2048);
            }
            #pragma unroll
            for (int mi = 0; mi < 4; mi++)
                #pragma unroll
                for (int ni = 0; ni < 4; ni++) {
                    int nj = ni >> 1, sel = ni & 1;
                    mma_bf16(acc[mi][ni], a[mi], bh[nj][sel], bh[nj][sel + 2]);
                    mma_bf16(acc[mi][ni], a[mi], bl[nj][sel], bl[nj][sel + 2]);
                }
            #pragma unroll
            for (int mi = 0; mi < 4; mi++)
                ldsm_x4(a[mi], adA + OFF_AL + mi * 2048);
            #pragma unroll
            for (int mi = 0; mi < 4; mi++)
                #pragma unroll
                for (int ni = 0; ni < 4; ni++) {
                    int nj = ni >> 1, sel = ni & 1;
                    mma_bf16(acc[mi][ni], a[mi], bh[nj][sel], bh[nj][sel + 2]);
                }
        }
        __syncthreads();
    }

    bool chalf = (ncb >= 256);
    int  cbase = chalf ? (ncb - 256) : ncb;
    #pragma unroll
    for (int mi = 0; mi < 4; mi++) {
        int row0 = brow + wm + mi * 16 + (lane >> 2);
        int row1 = row0 + 8;
        #pragma unroll
        for (int ni = 0; ni < 4; ni++) {
            int gcol = cbase + wn + ni * 8 + (lane & 3) * 2;
            float2 bb = *(const float2*)(bias + (chalf ? 256 : 0) + gcol);
            float2 v0, v1;
            v0.x = acc[mi][ni][0] + bb.x; v0.y = acc[mi][ni][1] + bb.y;
            v1.x = acc[mi][ni][2] + bb.x; v1.y = acc[mi][ni][3] + bb.y;
            if (!chalf) {
                if (row0 < M) *(float2*)(Bout + (size_t)row0 * 256 + gcol) = v0;
                if (row1 < M) *(float2*)(Bout + (size_t)row1 * 256 + gcol) = v1;
            } else {
                if (row0 < M) {
                    float di = dinv[row0];
                    *(float2*)(Cout + (size_t)row0 * 256 + gcol) = v0;
                    *(__half2*)(Yh + (size_t)row0 * 256 + gcol) =
                        __floats2half2_rn(di * v0.x, di * v0.y);
                }
                if (row1 < M) {
                    float di = dinv[row1];
                    *(float2*)(Cout + (size_t)row1 * 256 + gcol) = v1;
                    *(__half2*)(Yh + (size_t)row1 * 256 + gcol) =
                        __floats2half2_rn(di * v1.x, di * v1.y);
                }
            }
        }
    }
}

// ---------------- fused aggregate + mix + l2norm + relu --------------------
// gathers fp16 Yh rows with plain adds (R4 data flow, half the bytes).
// FINAL=0: emit bf16 hi/lo for next GEMM. FINAL=1: fuse out = h@W2 + b2.
template <int FINAL>
__global__ __launch_bounds__(256)
void agg_combine_kernel(const float* __restrict__ Bm, const float* __restrict__ C,
                        const __half* __restrict__ Yh,
                        const float* __restrict__ W2,
                        const float* __restrict__ b2,
                        float* __restrict__ Out, int M)
{
    int i = blockIdx.x;
    int t = threadIdx.x;
    if (i >= M) return;

    __shared__ int cols[256];
    __shared__ float wsum[8];
    __shared__ float s_h[256];

    int s = g_rowstart[i];
    int e = s + g_cnt[i];
    float a0 = 0.f, a1 = 0.f, a2 = 0.f, a3 = 0.f;
    float a4 = 0.f, a5 = 0.f, a6 = 0.f, a7 = 0.f;
    for (int base = s; base < e; base += 256) {
        int m = min(256, e - base);
        if (t < m) cols[t] = g_colidx[base + t];
        __syncthreads();
        int j = 0;
        for (; j + 8 <= m; j += 8) {
            a0 += __half2float(Yh[(size_t)cols[j]     * D_DIM + t]);
            a1 += __half2float(Yh[(size_t)cols[j + 1] * D_DIM + t]);
            a2 += __half2float(Yh[(size_t)cols[j + 2] * D_DIM + t]);
            a3 += __half2float(Yh[(size_t)cols[j + 3] * D_DIM + t]);
            a4 += __half2float(Yh[(size_t)cols[j + 4] * D_DIM + t]);
            a5 += __half2float(Yh[(size_t)cols[j + 5] * D_DIM + t]);
            a6 += __half2float(Yh[(size_t)cols[j + 6] * D_DIM + t]);
            a7 += __half2float(Yh[(size_t)cols[j + 7] * D_DIM + t]);
        }
        for (; j < m; j++)
            a0 += __half2float(Yh[(size_t)cols[j] * D_DIM + t]);
        __syncthreads();
    }
    float acc = ((a0 + a1) + (a2 + a3)) + ((a4 + a5) + (a6 + a7));

    float di = g_dinv[i];
    float nb = C[(size_t)i * D_DIM + t];
    float prop = di * acc + di * di * nb;
    float h = Bm[(size_t)i * D_DIM + t] + 0.5f * prop + 0.5f * nb;

    float v = h * h;
    #pragma unroll
    for (int o = 16; o > 0; o >>= 1)
        v += __shfl_xor_sync(0xffffffffu, v, o);
    if ((t & 31) == 0) wsum[t >> 5] = v;
    __syncthreads();
    float tot = 0.0f;
    #pragma unroll
    for (int w = 0; w < 8; w++) tot += wsum[w];
    float nrm = sqrtf(tot);
    h = fmaxf(h / fmaxf(nrm, 1e-12f), 0.0f);

    if (FINAL == 0) {
        __nv_bfloat16 hi = __float2bfloat16(h);
        size_t off = (size_t)i * D_DIM + t;
        g_Ah[off] = hi;
        g_Al[off] = __float2bfloat16(h - __bfloat162float(hi));
    } else {
        s_h[t] = h;
        __syncthreads();
        int wrp = t >> 5, lane = t & 31;
        int o = wrp * 4 + (lane >> 3);
        int jj = lane & 7;
        float oacc = 0.0f;
        #pragma unroll 8
        for (int j = jj; j < 256; j += 8)
            oacc = fmaf(s_h[j], __ldg(W2 + j * 32 + o), oacc);
        oacc += __shfl_xor_sync(0xffffffffu, oacc, 1);
        oacc += __shfl_xor_sync(0xffffffffu, oacc, 2);
        oacc += __shfl_xor_sync(0xffffffffu, oacc, 4);
        if (jj == 0)
            Out[(size_t)i * O_DIM + o] = oacc + __ldg(b2 + o);
    }
}

// ---------------- host launcher (single stream) ----------------------------
extern "C" void kernel_launch(void* const* d_in, const int* in_sizes, int n_in,
                              void* d_out, int out_size)
{
    const float* x   = (const float*)d_in[0];
    const int*   ei  = (const int*)  d_in[1];
    const float* W0  = (const float*)d_in[2];
    const float* b0  = (const float*)d_in[3];
    const float* Wn0 = (const float*)d_in[4];
    const float* bn0 = (const float*)d_in[5];
    const float* W1  = (const float*)d_in[6];
    const float* b1  = (const float*)d_in[7];
    const float* Wn1 = (const float*)d_in[8];
    const float* bn1 = (const float*)d_in[9];
    const float* W2  = (const float*)d_in[10];
    const float* b2  = (const float*)d_in[11];

    int M = in_sizes[0] / D_DIM;
    int E = in_sizes[1] / 2;
    const int* erow = ei;
    const int* ecol = ei + E;

    float *pB, *pC, *pBiasC, *pDinv;
    __half* pYh;
    __nv_bfloat16 *pAh, *pAl, *pWh, *pWl;
    int *pCnt, *pBase;
    cudaGetSymbolAddress((void**)&pB,    g_B);
    cudaGetSymbolAddress((void**)&pC,    g_C);
    cudaGetSymbolAddress((void**)&pYh,   g_Yh);
    cudaGetSymbolAddress((void**)&pDinv, g_dinv);
    cudaGetSymbolAddress((void**)&pAh,   g_Ah);
    cudaGetSymbolAddress((void**)&pAl,   g_Al);
    cudaGetSymbolAddress((void**)&pWh,   g_Wh);
    cudaGetSymbolAddress((void**)&pWl,   g_Wl);
    cudaGetSymbolAddress((void**)&pBiasC, g_biasC);
    cudaGetSymbolAddress((void**)&pCnt,  g_cnt);
    cudaGetSymbolAddress((void**)&pBase, g_base);

    static bool attr_done = false;
    if (!attr_done) {
        cudaFuncSetAttribute(hmma_gemm_kernel,
                             cudaFuncAttributeMaxDynamicSharedMemorySize,
                             2 * STAGE_BYTES + 256);
        attr_done = true;
    }

    int eb = (E + 255) / 256;
    int nb = (M + 255) / 256;
    dim3 gg((M + 127) / 128, 4);
    dim3 pgrid(8, 16), pblk(32, 8);

    // CSR build + dinv (before GEMM: its epilogue reads dinv)
    cudaMemsetAsync(pCnt, 0, (size_t)M * sizeof(int));
    cudaMemsetAsync(pBase, 0, sizeof(int));
    count_edges_kernel<<<eb, 256>>>(erow, E);
    offsets_kernel<<<nb, 256>>>(M);
    fill_csr_kernel<<<eb, 256>>>(erow, ecol, E);

    // weight prep (both layers)
    fuse_wb_kernel<<<257, 256>>>(W0, Wn0, b0, bn0, 0);
    pack_w_kernel<<<pgrid, pblk>>>(W0, b0, 0);
    fuse_wb_kernel<<<257, 256>>>(W1, Wn1, b1, bn1, 1);
    pack_w_kernel<<<pgrid, pblk>>>(W1, b1, 1);

    // split input
    split_kernel<<<(M * D_DIM / 4 + 255) / 256, 256>>>(x, M * D_DIM / 4);

    // layer 1
    hmma_gemm_kernel<<<gg, 256, 2 * STAGE_BYTES + 256>>>(
        pAh, pAl, pWh, pWl, pBiasC, pB, pC, pYh, pDinv, M);
    agg_combine_kernel<0><<<M, 256>>>(pB, pC, pYh, nullptr, nullptr, nullptr, M);

    // layer 2 + fused final layer
    hmma_gemm_kernel<<<gg, 256, 2 * STAGE_BYTES + 256>>>(
        pAh, pAl, pWh + 512 * 256, pWl + 512 * 256, pBiasC + 512,
        pB, pC, pYh, pDinv, M);
    agg_combine_kernel<1><<<M, 256>>>(pB, pC, pYh, W2, b2, (float*)d_out, M);
}

// round 11
// speedup vs baseline: 1.2404x; 1.2404x over previous
#include <cuda_runtime.h>
#include <cuda_bf16.h>
#include <cuda_fp16.h>
#include <math.h>
#include <stdint.h>

#define D_DIM 256
#define O_DIM 32
#define NMAX 50000
#define EMAX 800000

// ---------------- scratch (static device globals; no runtime allocation) ---
__device__ float g_B[(size_t)NMAX * D_DIM];   // h1 = A@W+b
__device__ float g_C[(size_t)NMAX * D_DIM];   // nb  (fused weights)
__device__ __half g_Yh[(size_t)NMAX * D_DIM]; // dinv * nb (fp16, gather source)
__device__ __nv_bfloat16 g_Ah[(size_t)NMAX * D_DIM];  // GEMM input hi
__device__ __nv_bfloat16 g_Al[(size_t)NMAX * D_DIM];  // GEMM input lo
__device__ __nv_bfloat16 g_Wh[2][512 * 256];  // packed weights [n][k] hi
__device__ __nv_bfloat16 g_Wl[2][512 * 256];  // packed weights [n][k] lo
__device__ float g_biasC[2][512];
__device__ float g_Wf[2][256 * 256];          // W @ Wn per layer
__device__ float g_bf[2][256];                // b @ Wn + bn per layer
__device__ float g_dinv[NMAX];
__device__ int   g_cnt[NMAX];
__device__ int   g_rowstart[NMAX];
__device__ int   g_cursor[NMAX];
__device__ int   g_colidx[EMAX];
__device__ int   g_base;                      // global slot cursor

// ================= helpers =================================================
__device__ __forceinline__ uint32_t smem_u32(const void* p) {
    uint32_t a;
    asm("{ .reg .u64 t; cvta.to.shared.u64 t, %1; cvt.u32.u64 %0, t; }"
        : "=r"(a) : "l"(p));
    return a;
}
__device__ __forceinline__ void ldsm_x4(uint32_t* r, uint32_t addr) {
    asm volatile("ldmatrix.sync.aligned.m8n8.x4.shared.b16 {%0,%1,%2,%3}, [%4];"
                 : "=r"(r[0]), "=r"(r[1]), "=r"(r[2]), "=r"(r[3]) : "r"(addr));
}
__device__ __forceinline__ void mma_bf16(float* c, const uint32_t* a,
                                         uint32_t b0, uint32_t b1) {
    asm volatile(
        "mma.sync.aligned.m16n8k16.row.col.f32.bf16.bf16.f32 "
        "{%0,%1,%2,%3}, {%4,%5,%6,%7}, {%8,%9}, {%0,%1,%2,%3};"
        : "+f"(c[0]), "+f"(c[1]), "+f"(c[2]), "+f"(c[3])
        : "r"(a[0]), "r"(a[1]), "r"(a[2]), "r"(a[3]), "r"(b0), "r"(b1));
}
__device__ __forceinline__ void cp16(uint32_t s, const void* g, bool p) {
    asm volatile("cp.async.cg.shared.global [%0], [%1], 16, %2;"
                 :: "r"(s), "l"(g), "r"(p ? 16 : 0));
}
#define CP_COMMIT() asm volatile("cp.async.commit_group;" ::: "memory")
#define CP_WAIT(n)  asm volatile("cp.async.wait_group %0;" :: "n"(n) : "memory")
#define SW128(off) ((off) ^ (((off) >> 3) & 0x70))

// ---------------- CSR build (scan-free) ------------------------------------
__global__ void count_edges_kernel(const int* __restrict__ row, int e) {
    int i = blockIdx.x * blockDim.x + threadIdx.x;
    if (i < e) atomicAdd(&g_cnt[row[i]], 1);
}
__global__ void offsets_kernel(int n) {
    int i = blockIdx.x * blockDim.x + threadIdx.x;
    int lane = threadIdx.x & 31;
    int c = (i < n) ? g_cnt[i] : 0;
    int incl = c;
    #pragma unroll
    for (int o = 1; o < 32; o <<= 1) {
        int v = __shfl_up_sync(0xffffffffu, incl, o);
        if (lane >= o) incl += v;
    }
    int total = __shfl_sync(0xffffffffu, incl, 31);
    int base = 0;
    if (lane == 31 && total > 0) base = atomicAdd(&g_base, total);
    base = __shfl_sync(0xffffffffu, base, 31);
    if (i < n) {
        int start = base + incl - c;
        g_rowstart[i] = start;
        g_cursor[i]   = start;
        g_dinv[i]     = rsqrtf((float)(c + 1));
    }
}
__global__ void fill_csr_kernel(const int* __restrict__ row,
                                const int* __restrict__ col, int e) {
    int i = blockIdx.x * blockDim.x + threadIdx.x;
    if (i < e) {
        int p = atomicAdd(&g_cursor[row[i]], 1);
        g_colidx[p] = col[i];
    }
}

// ---------------- weight prep ---------------------------------------------
__global__ void fuse_wb_kernel(const float* __restrict__ W,
                               const float* __restrict__ Wn,
                               const float* __restrict__ b,
                               const float* __restrict__ bn, int layer) {
    int n = threadIdx.x;
    int kb = blockIdx.x;
    if (kb < 256) {
        const float* wrow = W + kb * 256;
        float acc = 0.0f;
        #pragma unroll 8
        for (int j = 0; j < 256; j++)
            acc = fmaf(__ldg(wrow + j), Wn[j * 256 + n], acc);
        g_Wf[layer][kb * 256 + n] = acc;
    } else {
        float acc = bn[n];
        #pragma unroll 8
        for (int j = 0; j < 256; j++)
            acc = fmaf(__ldg(b + j), Wn[j * 256 + n], acc);
        g_bf[layer][n] = acc;
    }
}
__global__ void pack_w_kernel(const float* __restrict__ W,
                              const float* __restrict__ b, int layer) {
    __shared__ float s[32][33];
    int k0 = blockIdx.x * 32, n0 = blockIdx.y * 32;
    int tx = threadIdx.x, ty = threadIdx.y;
    #pragma unroll
    for (int i = 0; i < 4; i++) {
        int k = k0 + ty + i * 8;
        float v = (n0 < 256) ? W[k * 256 + n0 + tx]
                             : g_Wf[layer][k * 256 + (n0 - 256) + tx];
        s[ty + i * 8][tx] = v;
    }
    __syncthreads();
    #pragma unroll
    for (int i = 0; i < 4; i++) {
        int n = n0 + ty + i * 8;
        float w = s[tx][ty + i * 8];
        __nv_bfloat16 hi = __float2bfloat16(w);
        g_Wh[layer][n * 256 + k0 + tx] = hi;
        g_Wl[layer][n * 256 + k0 + tx] = __float2bfloat16(w - __bfloat162float(hi));
    }
    if (blockIdx.x == 0 && tx == 0) {
        #pragma unroll
        for (int i = 0; i < 4; i++) {
            int n = n0 + ty + i * 8;
            g_biasC[layer][n] = (n < 256) ? b[n] : g_bf[layer][n - 256];
        }
    }
}
__global__ void split_kernel(const float* __restrict__ x, int total4) {
    int i = blockIdx.x * blockDim.x + threadIdx.x;
    if (i < total4) {
        float4 v = reinterpret_cast<const float4*>(x)[i];
        __nv_bfloat16 h0 = __float2bfloat16(v.x), h1 = __float2bfloat16(v.y);
        __nv_bfloat16 h2 = __float2bfloat16(v.z), h3 = __float2bfloat16(v.w);
        __nv_bfloat162 hA, hB, lA, lB;
        hA.x = h0; hA.y = h1; hB.x = h2; hB.y = h3;
        lA.x = __float2bfloat16(v.x - __bfloat162float(h0));
        lA.y = __float2bfloat16(v.y - __bfloat162float(h1));
        lB.x = __float2bfloat16(v.z - __bfloat162float(h2));
        lB.y = __float2bfloat16(v.w - __bfloat162float(h3));
        reinterpret_cast<__nv_bfloat162*>(g_Ah)[i * 2]     = hA;
        reinterpret_cast<__nv_bfloat162*>(g_Ah)[i * 2 + 1] = hB;
        reinterpret_cast<__nv_bfloat162*>(g_Al)[i * 2]     = lA;
        reinterpret_cast<__nv_bfloat162*>(g_Al)[i * 2 + 1] = lB;
    }
}

// ---------------- HMMA GEMM: [B|C] = A @ Wcomb, split-bf16 x3 --------------
// R4 mainloop. Epilogue: B half -> Bout; C half -> Cout fp32 + Yh=dinv*C fp16.
#define STAGE_BYTES 65536
__global__ __launch_bounds__(256)
void hmma_gemm_kernel(const __nv_bfloat16* __restrict__ Ah,
                      const __nv_bfloat16* __restrict__ Al,
                      const __nv_bfloat16* __restrict__ Wh,
                      const __nv_bfloat16* __restrict__ Wl,
                      const float* __restrict__ bias,
                      float* __restrict__ Bout, float* __restrict__ Cout,
                      __half* __restrict__ Yh, const float* __restrict__ dinv,
                      int M)
{
    extern __shared__ char dsm_raw[];
    uint32_t dynu = smem_u32(dsm_raw);
    uint32_t pad = ((dynu + 127) & ~127u) - dynu;
    uint32_t sb = dynu + pad;
    const uint32_t OFF_AH = 0, OFF_AL = 16384, OFF_BH = 32768, OFF_BL = 49152;

    int tid  = threadIdx.x;
    int warp = tid >> 5, lane = tid & 31;
    int brow = blockIdx.x * 128;
    int ncb  = blockIdx.y * 128;
    int wm   = (warp >> 2) * 64;
    int wn   = (warp & 3) * 32;

    int lr  = tid >> 3;
    int lc8 = tid & 7;

    float acc[4][4][4];
    #pragma unroll
    for (int mi = 0; mi < 4; mi++)
        #pragma unroll
        for (int ni = 0; ni < 4; ni++)
            #pragma unroll
            for (int q = 0; q < 4; q++) acc[mi][ni][q] = 0.0f;

    auto load_chunk = [&](int chunk, int stage) {
        int k0 = chunk * 64;
        uint32_t sbase = sb + stage * STAGE_BYTES;
        #pragma unroll
        for (int l = 0; l < 4; l++) {
            int r = lr + l * 32;
            int gr = brow + r;
            bool p = gr < M;
            uint32_t sw = SW128((uint32_t)(r * 128 + lc8 * 16));
            size_t oa = (size_t)(p ? gr : 0) * 256 + k0 + lc8 * 8;
            cp16(sbase + OFF_AH + sw, Ah + oa, p);
            cp16(sbase + OFF_AL + sw, Al + oa, p);
            size_t ow = (size_t)(ncb + r) * 256 + k0 + lc8 * 8;
            cp16(sbase + OFF_BH + sw, Wh + ow, true);
            cp16(sbase + OFF_BL + sw, Wl + ow, true);
        }
        CP_COMMIT();
    };

    load_chunk(0, 0);

    for (int chunk = 0; chunk < 4; chunk++) {
        int stage = chunk & 1;
        if (chunk < 3) { load_chunk(chunk + 1, stage ^ 1); CP_WAIT(1); }
        else           { CP_WAIT(0); }
        __syncthreads();

        uint32_t sbase = sb + stage * STAGE_BYTES;
        #pragma unroll
        for (int ks = 0; ks < 4; ks++) {
            uint32_t kb   = (uint32_t)(ks * 32 + ((lane >> 4) & 1) * 16);
            uint32_t kswz = kb ^ ((uint32_t)(lane & 7) << 4);
            uint32_t rsub = (uint32_t)((lane & 7) + ((lane >> 3) & 1) * 8);

            uint32_t adA = sbase + (wm + rsub) * 128 + kswz;
            uint32_t adB = sbase + (wn + rsub) * 128 + kswz;

            uint32_t a[4][4];                    // reused: hi then lo
            uint32_t bh[2][4], bl[2][4];
            #pragma unroll
            for (int mi = 0; mi < 4; mi++)
                ldsm_x4(a[mi], adA + OFF_AH + mi * 2048);
            #pragma unroll
            for (int nj = 0; nj < 2; nj++) {
                ldsm_x4(bh[nj], adB + OFF_BH + nj * 2048);
                ldsm_x4(bl[nj], adB + OFF_BL + nj * 2048);
            }
            #pragma unroll
            for (int mi = 0; mi < 4; mi++)
                #pragma unroll
                for (int ni = 0; ni < 4; ni++) {
                    int nj = ni >> 1, sel = ni & 1;
                    mma_bf16(acc[mi][ni], a[mi], bh[nj][sel], bh[nj][sel + 2]);
                    mma_bf16(acc[mi][ni], a[mi], bl[nj][sel], bl[nj][sel + 2]);
                }
            #pragma unroll
            for (int mi = 0; mi < 4; mi++)
                ldsm_x4(a[mi], adA + OFF_AL + mi * 2048);
            #pragma unroll
            for (int mi = 0; mi < 4; mi++)
                #pragma unroll
                for (int ni = 0; ni < 4; ni++) {
                    int nj = ni >> 1, sel = ni & 1;
                    mma_bf16(acc[mi][ni], a[mi], bh[nj][sel], bh[nj][sel + 2]);
                }
        }
        __syncthreads();
    }

    bool chalf = (ncb >= 256);
    int  cbase = chalf ? (ncb - 256) : ncb;
    #pragma unroll
    for (int mi = 0; mi < 4; mi++) {
        int row0 = brow + wm + mi * 16 + (lane >> 2);
        int row1 = row0 + 8;
        #pragma unroll
        for (int ni = 0; ni < 4; ni++) {
            int gcol = cbase + wn + ni * 8 + (lane & 3) * 2;
            float2 bb = *(const float2*)(bias + (chalf ? 256 : 0) + gcol);
            float2 v0, v1;
            v0.x = acc[mi][ni][0] + bb.x; v0.y = acc[mi][ni][1] + bb.y;
            v1.x = acc[mi][ni][2] + bb.x; v1.y = acc[mi][ni][3] + bb.y;
            if (!chalf) {
                if (row0 < M) *(float2*)(Bout + (size_t)row0 * 256 + gcol) = v0;
                if (row1 < M) *(float2*)(Bout + (size_t)row1 * 256 + gcol) = v1;
            } else {
                if (row0 < M) {
                    float di = dinv[row0];
                    *(float2*)(Cout + (size_t)row0 * 256 + gcol) = v0;
                    *(__half2*)(Yh + (size_t)row0 * 256 + gcol) =
                        __floats2half2_rn(di * v0.x, di * v0.y);
                }
                if (row1 < M) {
                    float di = dinv[row1];
                    *(float2*)(Cout + (size_t)row1 * 256 + gcol) = v1;
                    *(__half2*)(Yh + (size_t)row1 * 256 + gcol) =
                        __floats2half2_rn(di * v1.x, di * v1.y);
                }
            }
        }
    }
}

// ---------------- fused aggregate + mix + l2norm + relu -> bf16 hi/lo ------
__global__ __launch_bounds__(256)
void agg_combine_kernel(const float* __restrict__ Bm, const float* __restrict__ C,
                        const __half* __restrict__ Yh, int M)
{
    int i = blockIdx.x;
    int t = threadIdx.x;
    if (i >= M) return;

    __shared__ int cols[256];
    __shared__ float wsum[8];

    int s = g_rowstart[i];
    int e = s + g_cnt[i];
    float a0 = 0.f, a1 = 0.f, a2 = 0.f, a3 = 0.f;
    float a4 = 0.f, a5 = 0.f, a6 = 0.f, a7 = 0.f;
    for (int base = s; base < e; base += 256) {
        int m = min(256, e - base);
        if (t < m) cols[t] = g_colidx[base + t];
        __syncthreads();
        int j = 0;
        for (; j + 8 <= m; j += 8) {
            a0 += __half2float(Yh[(size_t)cols[j]     * D_DIM + t]);
            a1 += __half2float(Yh[(size_t)cols[j + 1] * D_DIM + t]);
            a2 += __half2float(Yh[(size_t)cols[j + 2] * D_DIM + t]);
            a3 += __half2float(Yh[(size_t)cols[j + 3] * D_DIM + t]);
            a4 += __half2float(Yh[(size_t)cols[j + 4] * D_DIM + t]);
            a5 += __half2float(Yh[(size_t)cols[j + 5] * D_DIM + t]);
            a6 += __half2float(Yh[(size_t)cols[j + 6] * D_DIM + t]);
            a7 += __half2float(Yh[(size_t)cols[j + 7] * D_DIM + t]);
        }
        for (; j < m; j++)
            a0 += __half2float(Yh[(size_t)cols[j] * D_DIM + t]);
        __syncthreads();
    }
    float acc = ((a0 + a1) + (a2 + a3)) + ((a4 + a5) + (a6 + a7));

    float di = g_dinv[i];
    float nb = C[(size_t)i * D_DIM + t];
    float prop = di * acc + di * di * nb;
    float h = Bm[(size_t)i * D_DIM + t] + 0.5f * prop + 0.5f * nb;

    float v = h * h;
    #pragma unroll
    for (int o = 16; o > 0; o >>= 1)
        v += __shfl_xor_sync(0xffffffffu, v, o);
    if ((t & 31) == 0) wsum[t >> 5] = v;
    __syncthreads();
    float tot = 0.0f;
    #pragma unroll
    for (int w = 0; w < 8; w++) tot += wsum[w];
    float nrm = sqrtf(tot);
    h = fmaxf(h / fmaxf(nrm, 1e-12f), 0.0f);

    __nv_bfloat16 hi = __float2bfloat16(h);
    size_t off = (size_t)i * D_DIM + t;
    g_Ah[off] = hi;
    g_Al[off] = __float2bfloat16(h - __bfloat162float(hi));
}

// ---------------- output GEMM: Out[M,32] = (Hh+Hl) @ W2 + b2 ---------------
__global__ __launch_bounds__(256)
void gemm_out_kernel(const float* __restrict__ W2,
                     const float* __restrict__ b2, float* __restrict__ Out, int M)
{
    extern __shared__ __align__(16) float smem[];
    float* sW = smem;                 // [256][32] (32KB)
    float* sH = smem + D_DIM * 32;    // [32][256] (32KB)

    int tid  = threadIdx.x;
    int brow = blockIdx.x * 32;

    #pragma unroll
    for (int l = 0; l < 8; l++) {
        int idx = tid + l * 256;
        reinterpret_cast<float4*>(sW)[idx] = reinterpret_cast<const float4*>(W2)[idx];
    }
    #pragma unroll
    for (int l = 0; l < 16; l++) {
        int idx = tid + l * 256;       // bf16x2 index into 32x256 (4096 total)
        int r = idx >> 7, c2 = idx & 127;
        float2 f = make_float2(0.f, 0.f);
        if (brow + r < M) {
            size_t off = (size_t)(brow + r) * D_DIM + c2 * 2;
            __nv_bfloat162 hv = *(const __nv_bfloat162*)(g_Ah + off);
            __nv_bfloat162 lv = *(const __nv_bfloat162*)(g_Al + off);
            f.x = __bfloat162float(hv.x) + __bfloat162float(lv.x);
            f.y = __bfloat162float(hv.y) + __bfloat162float(lv.y);
        }
        *reinterpret_cast<float2*>(sH + r * D_DIM + c2 * 2) = f;
    }
    __syncthreads();

    int ry = tid >> 3;
    int c4 = (tid & 7) * 4;
    float4 acc = make_float4(0.f, 0.f, 0.f, 0.f);
    #pragma unroll 8
    for (int k = 0; k < D_DIM; k++) {
        float h = sH[ry * D_DIM + k];
        float4 w = *reinterpret_cast<const float4*>(&sW[k * 32 + c4]);
        acc.x = fmaf(h, w.x, acc.x);
        acc.y = fmaf(h, w.y, acc.y);
        acc.z = fmaf(h, w.z, acc.z);
        acc.w = fmaf(h, w.w, acc.w);
    }
    int grow = brow + ry;
    if (grow < M) {
        float4 bb = *reinterpret_cast<const float4*>(b2 + c4);
        acc.x += bb.x; acc.y += bb.y; acc.z += bb.z; acc.w += bb.w;
        *reinterpret_cast<float4*>(Out + (size_t)grow * O_DIM + c4) = acc;
    }
}

// ---------------- host launcher (single stream) ----------------------------
extern "C" void kernel_launch(void* const* d_in, const int* in_sizes, int n_in,
                              void* d_out, int out_size)
{
    const float* x   = (const float*)d_in[0];
    const int*   ei  = (const int*)  d_in[1];
    const float* W0  = (const float*)d_in[2];
    const float* b0  = (const float*)d_in[3];
    const float* Wn0 = (const float*)d_in[4];
    const float* bn0 = (const float*)d_in[5];
    const float* W1  = (const float*)d_in[6];
    const float* b1  = (const float*)d_in[7];
    const float* Wn1 = (const float*)d_in[8];
    const float* bn1 = (const float*)d_in[9];
    const float* W2  = (const float*)d_in[10];
    const float* b2  = (const float*)d_in[11];

    int M = in_sizes[0] / D_DIM;
    int E = in_sizes[1] / 2;
    const int* erow = ei;
    const int* ecol = ei + E;

    float *pB, *pC, *pBiasC, *pDinv;
    __half* pYh;
    __nv_bfloat16 *pAh, *pAl, *pWh, *pWl;
    int *pCnt, *pBase;
    cudaGetSymbolAddress((void**)&pB,    g_B);
    cudaGetSymbolAddress((void**)&pC,    g_C);
    cudaGetSymbolAddress((void**)&pYh,   g_Yh);
    cudaGetSymbolAddress((void**)&pDinv, g_dinv);
    cudaGetSymbolAddress((void**)&pAh,   g_Ah);
    cudaGetSymbolAddress((void**)&pAl,   g_Al);
    cudaGetSymbolAddress((void**)&pWh,   g_Wh);
    cudaGetSymbolAddress((void**)&pWl,   g_Wl);
    cudaGetSymbolAddress((void**)&pBiasC, g_biasC);
    cudaGetSymbolAddress((void**)&pCnt,  g_cnt);
    cudaGetSymbolAddress((void**)&pBase, g_base);

    static bool attr_done = false;
    if (!attr_done) {
        cudaFuncSetAttribute(hmma_gemm_kernel,
                             cudaFuncAttributeMaxDynamicSharedMemorySize,
                             2 * STAGE_BYTES + 256);
        cudaFuncSetAttribute(gemm_out_kernel,
                             cudaFuncAttributeMaxDynamicSharedMemorySize, 65536);
        attr_done = true;
    }

    int eb = (E + 255) / 256;
    int nb = (M + 255) / 256;
    dim3 gg((M + 127) / 128, 4);
    dim3 pgrid(8, 16), pblk(32, 8);

    // CSR build + dinv (before GEMM: its epilogue reads dinv)
    cudaMemsetAsync(pCnt, 0, (size_t)M * sizeof(int));
    cudaMemsetAsync(pBase, 0, sizeof(int));
    count_edges_kernel<<<eb, 256>>>(erow, E);
    offsets_kernel<<<nb, 256>>>(M);
    fill_csr_kernel<<<eb, 256>>>(erow, ecol, E);

    // weight prep (both layers)
    fuse_wb_kernel<<<257, 256>>>(W0, Wn0, b0, bn0, 0);
    pack_w_kernel<<<pgrid, pblk>>>(W0, b0, 0);
    fuse_wb_kernel<<<257, 256>>>(W1, Wn1, b1, bn1, 1);
    pack_w_kernel<<<pgrid, pblk>>>(W1, b1, 1);

    // split input
    split_kernel<<<(M * D_DIM / 4 + 255) / 256, 256>>>(x, M * D_DIM / 4);

    // layer 1
    hmma_gemm_kernel<<<gg, 256, 2 * STAGE_BYTES + 256>>>(
        pAh, pAl, pWh, pWl, pBiasC, pB, pC, pYh, pDinv, M);
    agg_combine_kernel<<<M, 256>>>(pB, pC, pYh, M);

    // layer 2
    hmma_gemm_kernel<<<gg, 256, 2 * STAGE_BYTES + 256>>>(
        pAh, pAl, pWh + 512 * 256, pWl + 512 * 256, pBiasC + 512,
        pB, pC, pYh, pDinv, M);
    agg_combine_kernel<<<M, 256>>>(pB, pC, pYh, M);

    // output layer
    gemm_out_kernel<<<(M + 31) / 32, 256, 65536>>>(W2, b2, (float*)d_out, M);
}

// round 12
// speedup vs baseline: 1.2647x; 1.0195x over previous
#include <cuda_runtime.h>
#include <cuda.h>
#include <cuda_bf16.h>
#include <cuda_fp16.h>
#include <math.h>
#include <stdint.h>

#define D_DIM 256
#define O_DIM 32
#define NMAX 50000
#define EMAX 800000

// ---------------- scratch (static device globals; no runtime allocation) ---
__device__ float g_B[(size_t)NMAX * D_DIM];   // h1 = A@W+b
__device__ float g_C[(size_t)NMAX * D_DIM];   // nb  (fused weights)
__device__ __half g_Yh[(size_t)NMAX * D_DIM]; // dinv * nb (fp16, gather source)
__device__ __align__(1024) __nv_bfloat16 g_Ah[(size_t)NMAX * D_DIM]; // input hi
__device__ __align__(1024) __nv_bfloat16 g_Al[(size_t)NMAX * D_DIM]; // input lo
__device__ __align__(1024) __nv_bfloat16 g_Wh[2][512 * 256];  // weights [n][k] hi
__device__ __align__(1024) __nv_bfloat16 g_Wl[2][512 * 256];  // weights [n][k] lo
__device__ float g_biasC[2][512];
__device__ float g_Wf[2][256 * 256];          // W @ Wn per layer
__device__ float g_bf[2][256];                // b @ Wn + bn per layer
__device__ float g_dinv[NMAX];
__device__ int   g_cnt[NMAX];
__device__ int   g_rowstart[NMAX];
__device__ int   g_cursor[NMAX];
__device__ int   g_colidx[EMAX];
__device__ int   g_base;                      // global slot cursor

// ================= helpers =================================================
__device__ __forceinline__ uint32_t smem_u32(const void* p) {
    uint32_t a;
    asm("{ .reg .u64 t; cvta.to.shared.u64 t, %1; cvt.u32.u64 %0, t; }"
        : "=r"(a) : "l"(p));
    return a;
}
__device__ __forceinline__ void ldsm_x4(uint32_t* r, uint32_t addr) {
    asm volatile("ldmatrix.sync.aligned.m8n8.x4.shared.b16 {%0,%1,%2,%3}, [%4];"
                 : "=r"(r[0]), "=r"(r[1]), "=r"(r[2]), "=r"(r[3]) : "r"(addr));
}
__device__ __forceinline__ void mma_bf16(float* c, const uint32_t* a,
                                         uint32_t b0, uint32_t b1) {
    asm volatile(
        "mma.sync.aligned.m16n8k16.row.col.f32.bf16.bf16.f32 "
        "{%0,%1,%2,%3}, {%4,%5,%6,%7}, {%8,%9}, {%0,%1,%2,%3};"
        : "+f"(c[0]), "+f"(c[1]), "+f"(c[2]), "+f"(c[3])
        : "r"(a[0]), "r"(a[1]), "r"(a[2]), "r"(a[3]), "r"(b0), "r"(b1));
}
__device__ __forceinline__ void tma2d(uint32_t smem, const CUtensorMap* map,
                                      int x, int y, uint32_t mbar) {
    asm volatile(
        "cp.async.bulk.tensor.2d.shared::cta.global.tile.mbarrier::complete_tx::bytes "
        "[%0], [%1, {%2, %3}], [%4];"
        :: "r"(smem), "l"(map), "r"(x), "r"(y), "r"(mbar) : "memory");
}
#define MBAR_INIT(mb, c)  asm volatile("mbarrier.init.shared.b64 [%0], %1;" :: "r"(mb), "r"(c) : "memory")
#define MBAR_EXPECT_TX(mb, tx) asm volatile("mbarrier.arrive.expect_tx.shared.b64 _, [%0], %1;" :: "r"(mb), "r"(tx) : "memory")
#define MBAR_WAIT(mb, par) do {                                              \
    uint32_t _mb = (mb), _p = (par), _done;                                  \
    asm volatile("{\n\t.reg .pred p;\n\t"                                    \
        "mbarrier.try_wait.parity.acquire.cta.shared::cta.b64 p, [%1], %2;\n\t" \
        "selp.b32 %0, 1, 0, p;\n\t}" : "=r"(_done) : "r"(_mb), "r"(_p) : "memory"); \
    if (!_done) {                                                            \
        asm volatile("{\n\t.reg .pred P1;\n\t"                               \
            "WL_%=:\n\t"                                                     \
            "mbarrier.try_wait.parity.acquire.cta.shared::cta.b64 P1, [%0], %1, 0x989680;\n\t" \
            "@P1 bra.uni WD_%=;\n\tbra.uni WL_%=;\n\tWD_%=:\n\t}"            \
            :: "r"(_mb), "r"(_p) : "memory");                                \
    }                                                                        \
} while (0)
#define SW128(off) ((off) ^ (((off) >> 3) & 0x70))

// ---------------- CSR build (scan-free) ------------------------------------
__global__ void count_edges_kernel(const int* __restrict__ row, int e) {
    int i = blockIdx.x * blockDim.x + threadIdx.x;
    if (i < e) atomicAdd(&g_cnt[row[i]], 1);
}
__global__ void offsets_kernel(int n) {
    int i = blockIdx.x * blockDim.x + threadIdx.x;
    int lane = threadIdx.x & 31;
    int c = (i < n) ? g_cnt[i] : 0;
    int incl = c;
    #pragma unroll
    for (int o = 1; o < 32; o <<= 1) {
        int v = __shfl_up_sync(0xffffffffu, incl, o);
        if (lane >= o) incl += v;
    }
    int total = __shfl_sync(0xffffffffu, incl, 31);
    int base = 0;
    if (lane == 31 && total > 0) base = atomicAdd(&g_base, total);
    base = __shfl_sync(0xffffffffu, base, 31);
    if (i < n) {
        int start = base + incl - c;
        g_rowstart[i] = start;
        g_cursor[i]   = start;
        g_dinv[i]     = rsqrtf((float)(c + 1));
    }
}
__global__ void fill_csr_kernel(const int* __restrict__ row,
                                const int* __restrict__ col, int e) {
    int i = blockIdx.x * blockDim.x + threadIdx.x;
    if (i < e) {
        int p = atomicAdd(&g_cursor[row[i]], 1);
        g_colidx[p] = col[i];
    }
}

// ---------------- weight prep ---------------------------------------------
__global__ void fuse_wb_kernel(const float* __restrict__ W,
                               const float* __restrict__ Wn,
                               const float* __restrict__ b,
                               const float* __restrict__ bn, int layer) {
    int n = threadIdx.x;
    int kb = blockIdx.x;
    if (kb < 256) {
        const float* wrow = W + kb * 256;
        float acc = 0.0f;
        #pragma unroll 8
        for (int j = 0; j < 256; j++)
            acc = fmaf(__ldg(wrow + j), Wn[j * 256 + n], acc);
        g_Wf[layer][kb * 256 + n] = acc;
    } else {
        float acc = bn[n];
        #pragma unroll 8
        for (int j = 0; j < 256; j++)
            acc = fmaf(__ldg(b + j), Wn[j * 256 + n], acc);
        g_bf[layer][n] = acc;
    }
}
__global__ void pack_w_kernel(const float* __restrict__ W,
                              const float* __restrict__ b, int layer) {
    __shared__ float s[32][33];
    int k0 = blockIdx.x * 32, n0 = blockIdx.y * 32;
    int tx = threadIdx.x, ty = threadIdx.y;
    #pragma unroll
    for (int i = 0; i < 4; i++) {
        int k = k0 + ty + i * 8;
        float v = (n0 < 256) ? W[k * 256 + n0 + tx]
                             : g_Wf[layer][k * 256 + (n0 - 256) + tx];
        s[ty + i * 8][tx] = v;
    }
    __syncthreads();
    #pragma unroll
    for (int i = 0; i < 4; i++) {
        int n = n0 + ty + i * 8;
        float w = s[tx][ty + i * 8];
        __nv_bfloat16 hi = __float2bfloat16(w);
        g_Wh[layer][n * 256 + k0 + tx] = hi;
        g_Wl[layer][n * 256 + k0 + tx] = __float2bfloat16(w - __bfloat162float(hi));
    }
    if (blockIdx.x == 0 && tx == 0) {
        #pragma unroll
        for (int i = 0; i < 4; i++) {
            int n = n0 + ty + i * 8;
            g_biasC[layer][n] = (n < 256) ? b[n] : g_bf[layer][n - 256];
        }
    }
}
__global__ void split_kernel(const float* __restrict__ x, int total4) {
    int i = blockIdx.x * blockDim.x + threadIdx.x;
    if (i < total4) {
        float4 v = reinterpret_cast<const float4*>(x)[i];
        __nv_bfloat16 h0 = __float2bfloat16(v.x), h1 = __float2bfloat16(v.y);
        __nv_bfloat16 h2 = __float2bfloat16(v.z), h3 = __float2bfloat16(v.w);
        __nv_bfloat162 hA, hB, lA, lB;
        hA.x = h0; hA.y = h1; hB.x = h2; hB.y = h3;
        lA.x = __float2bfloat16(v.x - __bfloat162float(h0));
        lA.y = __float2bfloat16(v.y - __bfloat162float(h1));
        lB.x = __float2bfloat16(v.z - __bfloat162float(h2));
        lB.y = __float2bfloat16(v.w - __bfloat162float(h3));
        reinterpret_cast<__nv_bfloat162*>(g_Ah)[i * 2]     = hA;
        reinterpret_cast<__nv_bfloat162*>(g_Ah)[i * 2 + 1] = hB;
        reinterpret_cast<__nv_bfloat162*>(g_Al)[i * 2]     = lA;
        reinterpret_cast<__nv_bfloat162*>(g_Al)[i * 2 + 1] = lB;
    }
}

// ---------------- HMMA GEMM: [B|C] = A @ Wcomb, split-bf16 x3, TMA loads ---
// CTA tile 128x128, BK=64, 2 x 64KB stages. TMA (cp.async.bulk.tensor.2d)
// replaces 16384 per-thread cp.asyncs with 16 bulk loads per CTA, removing
// the LDGSTS-issue bottleneck (8 cyc/op x 4096 ops/SMSP ~= 33K cyc/CTA).
#define STAGE_BYTES 65536
__global__ __launch_bounds__(256)
void hmma_gemm_kernel(const __grid_constant__ CUtensorMap tmAh,
                      const __grid_constant__ CUtensorMap tmAl,
                      const __grid_constant__ CUtensorMap tmWh,
                      const __grid_constant__ CUtensorMap tmWl,
                      int wyoff,
                      const float* __restrict__ bias,
                      float* __restrict__ Bout, float* __restrict__ Cout,
                      __half* __restrict__ Yh, const float* __restrict__ dinv,
                      int M)
{
    extern __shared__ char dsm_raw[];
    __shared__ __align__(8) unsigned long long s_mbar[2];
    uint32_t dynu = smem_u32(dsm_raw);
    uint32_t pad = ((dynu + 1023) & ~1023u) - dynu;
    uint32_t sb = dynu + pad;
    const uint32_t OFF_AH = 0, OFF_AL = 16384, OFF_BH = 32768, OFF_BL = 49152;

    int tid  = threadIdx.x;
    int warp = tid >> 5, lane = tid & 31;
    int brow = blockIdx.x * 128;
    int ncb  = blockIdx.y * 128;
    int wm   = (warp >> 2) * 64;
    int wn   = (warp & 3) * 32;

    uint32_t mb0 = smem_u32(&s_mbar[0]);
    uint32_t mb1 = smem_u32(&s_mbar[1]);
    if (tid == 0) { MBAR_INIT(mb0, 1); MBAR_INIT(mb1, 1); }
    __syncthreads();

    float acc[4][4][4];
    #pragma unroll
    for (int mi = 0; mi < 4; mi++)
        #pragma unroll
        for (int ni = 0; ni < 4; ni++)
            #pragma unroll
            for (int q = 0; q < 4; q++) acc[mi][ni][q] = 0.0f;

    auto load_chunk = [&](int chunk, int stage) {
        int k0 = chunk * 64;
        uint32_t sbase = sb + stage * STAGE_BYTES;
        uint32_t mb = stage ? mb1 : mb0;
        MBAR_EXPECT_TX(mb, (uint32_t)STAGE_BYTES);
        tma2d(sbase + OFF_AH, &tmAh, k0, brow, mb);
        tma2d(sbase + OFF_AL, &tmAl, k0, brow, mb);
        tma2d(sbase + OFF_BH, &tmWh, k0, wyoff + ncb, mb);
        tma2d(sbase + OFF_BL, &tmWl, k0, wyoff + ncb, mb);
    };

    if (tid == 0) load_chunk(0, 0);

    for (int chunk = 0; chunk < 4; chunk++) {
        int stage = chunk & 1;
        if (chunk < 3 && tid == 0) load_chunk(chunk + 1, stage ^ 1);
        MBAR_WAIT(stage ? mb1 : mb0, (chunk >> 1) & 1);

        uint32_t sbase = sb + stage * STAGE_BYTES;
        #pragma unroll
        for (int ks = 0; ks < 4; ks++) {
            uint32_t kb   = (uint32_t)(ks * 32 + ((lane >> 4) & 1) * 16);
            uint32_t kswz = kb ^ ((uint32_t)(lane & 7) << 4);
            uint32_t rsub = (uint32_t)((lane & 7) + ((lane >> 3) & 1) * 8);

            uint32_t adA = sbase + (wm + rsub) * 128 + kswz;
            uint32_t adB = sbase + (wn + rsub) * 128 + kswz;

            uint32_t a[4][4];                    // reused: hi then lo
            uint32_t bh[2][4], bl[2][4];
            #pragma unroll
            for (int mi = 0; mi < 4; mi++)
                ldsm_x4(a[mi], adA + OFF_AH + mi * 2048);
            #pragma unroll
            for (int nj = 0; nj < 2; nj++) {
                ldsm_x4(bh[nj], adB + OFF_BH + nj * 2048);
                ldsm_x4(bl[nj], adB + OFF_BL + nj * 2048);
            }
            #pragma unroll
            for (int mi = 0; mi < 4; mi++)
                #pragma unroll
                for (int ni = 0; ni < 4; ni++) {
                    int nj = ni >> 1, sel = ni & 1;
                    mma_bf16(acc[mi][ni], a[mi], bh[nj][sel], bh[nj][sel + 2]);
                    mma_bf16(acc[mi][ni], a[mi], bl[nj][sel], bl[nj][sel + 2]);
                }
            #pragma unroll
            for (int mi = 0; mi < 4; mi++)
                ldsm_x4(a[mi], adA + OFF_AL + mi * 2048);
            #pragma unroll
            for (int mi = 0; mi < 4; mi++)
                #pragma unroll
                for (int ni = 0; ni < 4; ni++) {
                    int nj = ni >> 1, sel = ni & 1;
                    mma_bf16(acc[mi][ni], a[mi], bh[nj][sel], bh[nj][sel + 2]);
                }
        }
        __syncthreads();
    }

    bool chalf = (ncb >= 256);
    int  cbase = chalf ? (ncb - 256) : ncb;
    #pragma unroll
    for (int mi = 0; mi < 4; mi++) {
        int row0 = brow + wm + mi * 16 + (lane >> 2);
        int row1 = row0 + 8;
        #pragma unroll
        for (int ni = 0; ni < 4; ni++) {
            int gcol = cbase + wn + ni * 8 + (lane & 3) * 2;
            float2 bb = *(const float2*)(bias + (chalf ? 256 : 0) + gcol);
            float2 v0, v1;
            v0.x = acc[mi][ni][0] + bb.x; v0.y = acc[mi][ni][1] + bb.y;
            v1.x = acc[mi][ni][2] + bb.x; v1.y = acc[mi][ni][3] + bb.y;
            if (!chalf) {
                if (row0 < M) *(float2*)(Bout + (size_t)row0 * 256 + gcol) = v0;
                if (row1 < M) *(float2*)(Bout + (size_t)row1 * 256 + gcol) = v1;
            } else {
                if (row0 < M) {
                    float di = dinv[row0];
                    *(float2*)(Cout + (size_t)row0 * 256 + gcol) = v0;
                    *(__half2*)(Yh + (size_t)row0 * 256 + gcol) =
                        __floats2half2_rn(di * v0.x, di * v0.y);
                }
                if (row1 < M) {
                    float di = dinv[row1];
                    *(float2*)(Cout + (size_t)row1 * 256 + gcol) = v1;
                    *(__half2*)(Yh + (size_t)row1 * 256 + gcol) =
                        __floats2half2_rn(di * v1.x, di * v1.y);
                }
            }
        }
    }
}

// ---------------- fused aggregate + mix + l2norm + relu -> bf16 hi/lo ------
__global__ __launch_bounds__(256)
void agg_combine_kernel(const float* __restrict__ Bm, const float* __restrict__ C,
                        const __half* __restrict__ Yh, int M)
{
    int i = blockIdx.x;
    int t = threadIdx.x;
    if (i >= M) return;

    __shared__ int cols[256];
    __shared__ float wsum[8];

    int s = g_rowstart[i];
    int e = s + g_cnt[i];
    float a0 = 0.f, a1 = 0.f, a2 = 0.f, a3 = 0.f;
    float a4 = 0.f, a5 = 0.f, a6 = 0.f, a7 = 0.f;
    for (int base = s; base < e; base += 256) {
        int m = min(256, e - base);
        if (t < m) cols[t] = g_colidx[base + t];
        __syncthreads();
        int j = 0;
        for (; j + 8 <= m; j += 8) {
            a0 += __half2float(Yh[(size_t)cols[j]     * D_DIM + t]);
            a1 += __half2float(Yh[(size_t)cols[j + 1] * D_DIM + t]);
            a2 += __half2float(Yh[(size_t)cols[j + 2] * D_DIM + t]);
            a3 += __half2float(Yh[(size_t)cols[j + 3] * D_DIM + t]);
            a4 += __half2float(Yh[(size_t)cols[j + 4] * D_DIM + t]);
            a5 += __half2float(Yh[(size_t)cols[j + 5] * D_DIM + t]);
            a6 += __half2float(Yh[(size_t)cols[j + 6] * D_DIM + t]);
            a7 += __half2float(Yh[(size_t)cols[j + 7] * D_DIM + t]);
        }
        for (; j < m; j++)
            a0 += __half2float(Yh[(size_t)cols[j] * D_DIM + t]);
        __syncthreads();
    }
    float acc = ((a0 + a1) + (a2 + a3)) + ((a4 + a5) + (a6 + a7));

    float di = g_dinv[i];
    float nb = C[(size_t)i * D_DIM + t];
    float prop = di * acc + di * di * nb;
    float h = Bm[(size_t)i * D_DIM + t] + 0.5f * prop + 0.5f * nb;

    float v = h * h;
    #pragma unroll
    for (int o = 16; o > 0; o >>= 1)
        v += __shfl_xor_sync(0xffffffffu, v, o);
    if ((t & 31) == 0) wsum[t >> 5] = v;
    __syncthreads();
    float tot = 0.0f;
    #pragma unroll
    for (int w = 0; w < 8; w++) tot += wsum[w];
    float nrm = sqrtf(tot);
    h = fmaxf(h / fmaxf(nrm, 1e-12f), 0.0f);

    __nv_bfloat16 hi = __float2bfloat16(h);
    size_t off = (size_t)i * D_DIM + t;
    g_Ah[off] = hi;
    g_Al[off] = __float2bfloat16(h - __bfloat162float(hi));
}

// ---------------- output GEMM: Out[M,32] = (Hh+Hl) @ W2 + b2 ---------------
__global__ __launch_bounds__(256)
void gemm_out_kernel(const float* __restrict__ W2,
                     const float* __restrict__ b2, float* __restrict__ Out, int M)
{
    extern __shared__ __align__(16) float smem[];
    float* sW = smem;                 // [256][32] (32KB)
    float* sH = smem + D_DIM * 32;    // [32][256] (32KB)

    int tid  = threadIdx.x;
    int brow = blockIdx.x * 32;

    #pragma unroll
    for (int l = 0; l < 8; l++) {
        int idx = tid + l * 256;
        reinterpret_cast<float4*>(sW)[idx] = reinterpret_cast<const float4*>(W2)[idx];
    }
    #pragma unroll
    for (int l = 0; l < 16; l++) {
        int idx = tid + l * 256;       // bf16x2 index into 32x256 (4096 total)
        int r = idx >> 7, c2 = idx & 127;
        float2 f = make_float2(0.f, 0.f);
        if (brow + r < M) {
            size_t off = (size_t)(brow + r) * D_DIM + c2 * 2;
            __nv_bfloat162 hv = *(const __nv_bfloat162*)(g_Ah + off);
            __nv_bfloat162 lv = *(const __nv_bfloat162*)(g_Al + off);
            f.x = __bfloat162float(hv.x) + __bfloat162float(lv.x);
            f.y = __bfloat162float(hv.y) + __bfloat162float(lv.y);
        }
        *reinterpret_cast<float2*>(sH + r * D_DIM + c2 * 2) = f;
    }
    __syncthreads();

    int ry = tid >> 3;
    int c4 = (tid & 7) * 4;
    float4 acc = make_float4(0.f, 0.f, 0.f, 0.f);
    #pragma unroll 8
    for (int k = 0; k < D_DIM; k++) {
        float h = sH[ry * D_DIM + k];
        float4 w = *reinterpret_cast<const float4*>(&sW[k * 32 + c4]);
        acc.x = fmaf(h, w.x, acc.x);
        acc.y = fmaf(h, w.y, acc.y);
        acc.z = fmaf(h, w.z, acc.z);
        acc.w = fmaf(h, w.w, acc.w);
    }
    int grow = brow + ry;
    if (grow < M) {
        float4 bb = *reinterpret_cast<const float4*>(b2 + c4);
        acc.x += bb.x; acc.y += bb.y; acc.z += bb.z; acc.w += bb.w;
        *reinterpret_cast<float4*>(Out + (size_t)grow * O_DIM + c4) = acc;
    }
}

// ---------------- host launcher (single stream) ----------------------------
typedef CUresult (CUDAAPI *PFN_encTiled)(
    CUtensorMap*, CUtensorMapDataType, cuuint32_t, void*,
    const cuuint64_t*, const cuuint64_t*, const cuuint32_t*, const cuuint32_t*,
    CUtensorMapInterleave, CUtensorMapSwizzle, CUtensorMapL2promotion,
    CUtensorMapFloatOOBfill);

extern "C" void kernel_launch(void* const* d_in, const int* in_sizes, int n_in,
                              void* d_out, int out_size)
{
    const float* x   = (const float*)d_in[0];
    const int*   ei  = (const int*)  d_in[1];
    const float* W0  = (const float*)d_in[2];
    const float* b0  = (const float*)d_in[3];
    const float* Wn0 = (const float*)d_in[4];
    const float* bn0 = (const float*)d_in[5];
    const float* W1  = (const float*)d_in[6];
    const float* b1  = (const float*)d_in[7];
    const float* Wn1 = (const float*)d_in[8];
    const float* bn1 = (const float*)d_in[9];
    const float* W2  = (const float*)d_in[10];
    const float* b2  = (const float*)d_in[11];

    int M = in_sizes[0] / D_DIM;
    int E = in_sizes[1] / 2;
    const int* erow = ei;
    const int* ecol = ei + E;

    float *pB, *pC, *pBiasC, *pDinv;
    __half* pYh;
    __nv_bfloat16 *pAh, *pAl, *pWh, *pWl;
    int *pCnt, *pBase;
    cudaGetSymbolAddress((void**)&pB,    g_B);
    cudaGetSymbolAddress((void**)&pC,    g_C);
    cudaGetSymbolAddress((void**)&pYh,   g_Yh);
    cudaGetSymbolAddress((void**)&pDinv, g_dinv);
    cudaGetSymbolAddress((void**)&pAh,   g_Ah);
    cudaGetSymbolAddress((void**)&pAl,   g_Al);
    cudaGetSymbolAddress((void**)&pWh,   g_Wh);
    cudaGetSymbolAddress((void**)&pWl,   g_Wl);
    cudaGetSymbolAddress((void**)&pBiasC, g_biasC);
    cudaGetSymbolAddress((void**)&pCnt,  g_cnt);
    cudaGetSymbolAddress((void**)&pBase, g_base);

    static CUtensorMap tmAh, tmAl, tmWh, tmWl;
    static bool init_done = false;
    if (!init_done) {
        cudaFuncSetAttribute(hmma_gemm_kernel,
                             cudaFuncAttributeMaxDynamicSharedMemorySize,
                             2 * STAGE_BYTES + 1024);
        cudaFuncSetAttribute(gemm_out_kernel,
                             cudaFuncAttributeMaxDynamicSharedMemorySize, 65536);

        void* fp = nullptr;
        cudaDriverEntryPointQueryResult qr;
#if CUDART_VERSION >= 12050
        cudaGetDriverEntryPointByVersion("cuTensorMapEncodeTiled", &fp, 12000,
                                         cudaEnableDefault, &qr);
#else
        cudaGetDriverEntryPoint("cuTensorMapEncodeTiled", &fp,
                                cudaEnableDefault, &qr);
#endif
        PFN_encTiled enc = (PFN_encTiled)fp;

        cuuint64_t dimsA[2] = {256, (cuuint64_t)M};
        cuuint64_t strA[1]  = {256 * 2};
        cuuint64_t dimsW[2] = {256, 1024};
        cuuint64_t strW[1]  = {256 * 2};
        cuuint32_t box[2]   = {64, 128};
        cuuint32_t estr[2]  = {1, 1};
        enc(&tmAh, CU_TENSOR_MAP_DATA_TYPE_BFLOAT16, 2, pAh, dimsA, strA, box,
            estr, CU_TENSOR_MAP_INTERLEAVE_NONE, CU_TENSOR_MAP_SWIZZLE_128B,
            CU_TENSOR_MAP_L2_PROMOTION_L2_128B, CU_TENSOR_MAP_FLOAT_OOB_FILL_NONE);
        enc(&tmAl, CU_TENSOR_MAP_DATA_TYPE_BFLOAT16, 2, pAl, dimsA, strA, box,
            estr, CU_TENSOR_MAP_INTERLEAVE_NONE, CU_TENSOR_MAP_SWIZZLE_128B,
            CU_TENSOR_MAP_L2_PROMOTION_L2_128B, CU_TENSOR_MAP_FLOAT_OOB_FILL_NONE);
        enc(&tmWh, CU_TENSOR_MAP_DATA_TYPE_BFLOAT16, 2, pWh, dimsW, strW, box,
            estr, CU_TENSOR_MAP_INTERLEAVE_NONE, CU_TENSOR_MAP_SWIZZLE_128B,
            CU_TENSOR_MAP_L2_PROMOTION_L2_128B, CU_TENSOR_MAP_FLOAT_OOB_FILL_NONE);
        enc(&tmWl, CU_TENSOR_MAP_DATA_TYPE_BFLOAT16, 2, pWl, dimsW, strW, box,
            estr, CU_TENSOR_MAP_INTERLEAVE_NONE, CU_TENSOR_MAP_SWIZZLE_128B,
            CU_TENSOR_MAP_L2_PROMOTION_L2_128B, CU_TENSOR_MAP_FLOAT_OOB_FILL_NONE);
        init_done = true;
    }

    int eb = (E + 255) / 256;
    int nb = (M + 255) / 256;
    dim3 gg((M + 127) / 128, 4);
    dim3 pgrid(8, 16), pblk(32, 8);

    // CSR build + dinv (before GEMM: its epilogue reads dinv)
    cudaMemsetAsync(pCnt, 0, (size_t)M * sizeof(int));
    cudaMemsetAsync(pBase, 0, sizeof(int));
    count_edges_kernel<<<eb, 256>>>(erow, E);
    offsets_kernel<<<nb, 256>>>(M);
    fill_csr_kernel<<<eb, 256>>>(erow, ecol, E);

    // weight prep (both layers)
    fuse_wb_kernel<<<257, 256>>>(W0, Wn0, b0, bn0, 0);
    pack_w_kernel<<<pgrid, pblk>>>(W0, b0, 0);
    fuse_wb_kernel<<<257, 256>>>(W1, Wn1, b1, bn1, 1);
    pack_w_kernel<<<pgrid, pblk>>>(W1, b1, 1);

    // split input
    split_kernel<<<(M * D_DIM / 4 + 255) / 256, 256>>>(x, M * D_DIM / 4);

    // layer 1
    hmma_gemm_kernel<<<gg, 256, 2 * STAGE_BYTES + 1024>>>(
        tmAh, tmAl, tmWh, tmWl, 0, pBiasC, pB, pC, pYh, pDinv, M);
    agg_combine_kernel<<<M, 256>>>(pB, pC, pYh, M);

    // layer 2
    hmma_gemm_kernel<<<gg, 256, 2 * STAGE_BYTES + 1024>>>(
        tmAh, tmAl, tmWh, tmWl, 512, pBiasC + 512, pB, pC, pYh, pDinv, M);
    agg_combine_kernel<<<M, 256>>>(pB, pC, pYh, M);

    // output layer
    gemm_out_kernel<<<(M + 31) / 32, 256, 65536>>>(W2, b2, (float*)d_out, M);
}

// round 13
// speedup vs baseline: 1.5155x; 1.1983x over previous
#include <cuda_runtime.h>
#include <cuda.h>
#include <cuda_bf16.h>
#include <cuda_fp16.h>
#include <math.h>
#include <stdint.h>

#define D_DIM 256
#define O_DIM 32
#define NMAX 50000
#define EMAX 800000

// ---------------- scratch (static device globals; no runtime allocation) ---
__device__ float g_B[(size_t)NMAX * D_DIM];   // h1 = A@W+b
__device__ float g_C[(size_t)NMAX * D_DIM];   // nb  (fused weights)
__device__ __align__(1024) __half g_Yh[(size_t)NMAX * D_DIM]; // dinv*nb fp16
__device__ __align__(1024) __nv_bfloat16 g_Ah[(size_t)NMAX * D_DIM]; // input hi
__device__ __align__(1024) __nv_bfloat16 g_Al[(size_t)NMAX * D_DIM]; // input lo
__device__ __align__(1024) __nv_bfloat16 g_Wh[2][512 * 256];  // weights [n][k] hi
__device__ __align__(1024) __nv_bfloat16 g_Wl[2][512 * 256];  // weights [n][k] lo
__device__ float g_biasC[2][512];
__device__ float g_WfP[2][2][256 * 256];      // partial W@Wn (layer, k-half)
__device__ float g_bfP[2][2][256];            // partial b@Wn + bn
__device__ float g_dinv[NMAX];
__device__ int   g_cnt[NMAX];
__device__ int   g_rowstart[NMAX];
__device__ int   g_cursor[NMAX];
__device__ int   g_colidx[EMAX];
__device__ int   g_base;                      // global slot cursor

// ================= helpers =================================================
__device__ __forceinline__ uint32_t smem_u32(const void* p) {
    uint32_t a;
    asm("{ .reg .u64 t; cvta.to.shared.u64 t, %1; cvt.u32.u64 %0, t; }"
        : "=r"(a) : "l"(p));
    return a;
}
__device__ __forceinline__ void ldsm_x4(uint32_t* r, uint32_t addr) {
    asm volatile("ldmatrix.sync.aligned.m8n8.x4.shared.b16 {%0,%1,%2,%3}, [%4];"
                 : "=r"(r[0]), "=r"(r[1]), "=r"(r[2]), "=r"(r[3]) : "r"(addr));
}
__device__ __forceinline__ void mma_bf16(float* c, const uint32_t* a,
                                         uint32_t b0, uint32_t b1) {
    asm volatile(
        "mma.sync.aligned.m16n8k16.row.col.f32.bf16.bf16.f32 "
        "{%0,%1,%2,%3}, {%4,%5,%6,%7}, {%8,%9}, {%0,%1,%2,%3};"
        : "+f"(c[0]), "+f"(c[1]), "+f"(c[2]), "+f"(c[3])
        : "r"(a[0]), "r"(a[1]), "r"(a[2]), "r"(a[3]), "r"(b0), "r"(b1));
}
__device__ __forceinline__ void tma2d(uint32_t smem, const CUtensorMap* map,
                                      int x, int y, uint32_t mbar) {
    asm volatile(
        "cp.async.bulk.tensor.2d.shared::cta.global.tile.mbarrier::complete_tx::bytes "
        "[%0], [%1, {%2, %3}], [%4];"
        :: "r"(smem), "l"(map), "r"(x), "r"(y), "r"(mbar) : "memory");
}
#define MBAR_INIT(mb, c)  asm volatile("mbarrier.init.shared.b64 [%0], %1;" :: "r"(mb), "r"(c) : "memory")
#define MBAR_EXPECT_TX(mb, tx) asm volatile("mbarrier.arrive.expect_tx.shared.b64 _, [%0], %1;" :: "r"(mb), "r"(tx) : "memory")
#define MBAR_WAIT(mb, par) do {                                              \
    uint32_t _mb = (mb), _p = (par), _done;                                  \
    asm volatile("{\n\t.reg .pred p;\n\t"                                    \
        "mbarrier.try_wait.parity.acquire.cta.shared::cta.b64 p, [%1], %2;\n\t" \
        "selp.b32 %0, 1, 0, p;\n\t}" : "=r"(_done) : "r"(_mb), "r"(_p) : "memory"); \
    if (!_done) {                                                            \
        asm volatile("{\n\t.reg .pred P1;\n\t"                               \
            "WL_%=:\n\t"                                                     \
            "mbarrier.try_wait.parity.acquire.cta.shared::cta.b64 P1, [%0], %1, 0x989680;\n\t" \
            "@P1 bra.uni WD_%=;\n\tbra.uni WL_%=;\n\tWD_%=:\n\t}"            \
            :: "r"(_mb), "r"(_p) : "memory");                                \
    }                                                                        \
} while (0)
#define SW128(off) ((off) ^ (((off) >> 3) & 0x70))

// ---------------- CSR build (scan-free) ------------------------------------
__global__ void count_edges_kernel(const int* __restrict__ row, int e) {
    int i = blockIdx.x * blockDim.x + threadIdx.x;
    if (i < e) atomicAdd(&g_cnt[row[i]], 1);
}
__global__ void offsets_kernel(int n) {
    int i = blockIdx.x * blockDim.x + threadIdx.x;
    int lane = threadIdx.x & 31;
    int c = (i < n) ? g_cnt[i] : 0;
    int incl = c;
    #pragma unroll
    for (int o = 1; o < 32; o <<= 1) {
        int v = __shfl_up_sync(0xffffffffu, incl, o);
        if (lane >= o) incl += v;
    }
    int total = __shfl_sync(0xffffffffu, incl, 31);
    int base = 0;
    if (lane == 31 && total > 0) base = atomicAdd(&g_base, total);
    base = __shfl_sync(0xffffffffu, base, 31);
    if (i < n) {
        int start = base + incl - c;
        g_rowstart[i] = start;
        g_cursor[i]   = start;
        g_dinv[i]     = rsqrtf((float)(c + 1));
    }
}
__global__ void fill_csr_kernel(const int* __restrict__ row,
                                const int* __restrict__ col, int e) {
    int i = blockIdx.x * blockDim.x + threadIdx.x;
    if (i < e) {
        int p = atomicAdd(&g_cursor[row[i]], 1);
        g_colidx[p] = col[i];
    }
}

// ---------------- weight prep (both layers, k-split x2 in one launch) ------
__global__ void fuse_wb_kernel(const float* __restrict__ W0,
                               const float* __restrict__ Wn0,
                               const float* __restrict__ b0,
                               const float* __restrict__ bn0,
                               const float* __restrict__ W1,
                               const float* __restrict__ Wn1,
                               const float* __restrict__ b1,
                               const float* __restrict__ bn1) {
    int layer = blockIdx.y, part = blockIdx.z;
    const float* W  = layer ? W1  : W0;
    const float* Wn = layer ? Wn1 : Wn0;
    const float* b  = layer ? b1  : b0;
    const float* bn = layer ? bn1 : bn0;
    int n = threadIdx.x;
    int kb = blockIdx.x;
    int j0 = part * 128;
    if (kb < 256) {
        const float* wrow = W + kb * 256 + j0;
        const float* wncol = Wn + (size_t)j0 * 256 + n;
        float acc = 0.0f;
        #pragma unroll 8
        for (int j = 0; j < 128; j++)
            acc = fmaf(__ldg(wrow + j), wncol[j * 256], acc);
        g_WfP[layer][part][kb * 256 + n] = acc;
    } else {
        float acc = (part == 0) ? bn[n] : 0.0f;
        #pragma unroll 8
        for (int j = 0; j < 128; j++)
            acc = fmaf(__ldg(b + j0 + j), Wn[(size_t)(j0 + j) * 256 + n], acc);
        g_bfP[layer][part][n] = acc;
    }
}
__global__ void pack_w_kernel(const float* __restrict__ W0,
                              const float* __restrict__ b0,
                              const float* __restrict__ W1,
                              const float* __restrict__ b1) {
    __shared__ float s[32][33];
    int layer = blockIdx.z;
    const float* W = layer ? W1 : W0;
    const float* b = layer ? b1 : b0;
    int k0 = blockIdx.x * 32, n0 = blockIdx.y * 32;
    int tx = threadIdx.x, ty = threadIdx.y;
    #pragma unroll
    for (int i = 0; i < 4; i++) {
        int k = k0 + ty + i * 8;
        float v;
        if (n0 < 256) v = W[k * 256 + n0 + tx];
        else {
            int idx = k * 256 + (n0 - 256) + tx;
            v = g_WfP[layer][0][idx] + g_WfP[layer][1][idx];
        }
        s[ty + i * 8][tx] = v;
    }
    __syncthreads();
    #pragma unroll
    for (int i = 0; i < 4; i++) {
        int n = n0 + ty + i * 8;
        float w = s[tx][ty + i * 8];
        __nv_bfloat16 hi = __float2bfloat16(w);
        g_Wh[layer][n * 256 + k0 + tx] = hi;
        g_Wl[layer][n * 256 + k0 + tx] = __float2bfloat16(w - __bfloat162float(hi));
    }
    if (blockIdx.x == 0 && tx == 0) {
        #pragma unroll
        for (int i = 0; i < 4; i++) {
            int n = n0 + ty + i * 8;
            g_biasC[layer][n] = (n < 256) ? b[n]
                : (g_bfP[layer][0][n - 256] + g_bfP[layer][1][n - 256]);
        }
    }
}
__global__ void split_kernel(const float* __restrict__ x, int total4) {
    int i = blockIdx.x * blockDim.x + threadIdx.x;
    if (i < total4) {
        float4 v = reinterpret_cast<const float4*>(x)[i];
        __nv_bfloat16 h0 = __float2bfloat16(v.x), h1 = __float2bfloat16(v.y);
        __nv_bfloat16 h2 = __float2bfloat16(v.z), h3 = __float2bfloat16(v.w);
        __nv_bfloat162 hA, hB, lA, lB;
        hA.x = h0; hA.y = h1; hB.x = h2; hB.y = h3;
        lA.x = __float2bfloat16(v.x - __bfloat162float(h0));
        lA.y = __float2bfloat16(v.y - __bfloat162float(h1));
        lB.x = __float2bfloat16(v.z - __bfloat162float(h2));
        lB.y = __float2bfloat16(v.w - __bfloat162float(h3));
        reinterpret_cast<__nv_bfloat162*>(g_Ah)[i * 2]     = hA;
        reinterpret_cast<__nv_bfloat162*>(g_Ah)[i * 2 + 1] = hB;
        reinterpret_cast<__nv_bfloat162*>(g_Al)[i * 2]     = lA;
        reinterpret_cast<__nv_bfloat162*>(g_Al)[i * 2 + 1] = lB;
    }
}

// ---------------- HMMA GEMM: [B|C] = A @ Wcomb, split-bf16 x3, TMA loads ---
#define STAGE_BYTES 65536
__global__ __launch_bounds__(256)
void hmma_gemm_kernel(const __grid_constant__ CUtensorMap tmAh,
                      const __grid_constant__ CUtensorMap tmAl,
                      const __grid_constant__ CUtensorMap tmWh,
                      const __grid_constant__ CUtensorMap tmWl,
                      int wyoff,
                      const float* __restrict__ bias,
                      float* __restrict__ Bout, float* __restrict__ Cout,
                      __half* __restrict__ Yh, const float* __restrict__ dinv,
                      int M)
{
    extern __shared__ char dsm_raw[];
    __shared__ __align__(8) unsigned long long s_mbar[2];
    uint32_t dynu = smem_u32(dsm_raw);
    uint32_t pad = ((dynu + 1023) & ~1023u) - dynu;
    uint32_t sb = dynu + pad;
    const uint32_t OFF_AH = 0, OFF_AL = 16384, OFF_BH = 32768, OFF_BL = 49152;

    int tid  = threadIdx.x;
    int warp = tid >> 5, lane = tid & 31;
    int brow = blockIdx.x * 128;
    int ncb  = blockIdx.y * 128;
    int wm   = (warp >> 2) * 64;
    int wn   = (warp & 3) * 32;

    uint32_t mb0 = smem_u32(&s_mbar[0]);
    uint32_t mb1 = smem_u32(&s_mbar[1]);
    if (tid == 0) { MBAR_INIT(mb0, 1); MBAR_INIT(mb1, 1); }
    __syncthreads();

    float acc[4][4][4];
    #pragma unroll
    for (int mi = 0; mi < 4; mi++)
        #pragma unroll
        for (int ni = 0; ni < 4; ni++)
            #pragma unroll
            for (int q = 0; q < 4; q++) acc[mi][ni][q] = 0.0f;

    auto load_chunk = [&](int chunk, int stage) {
        int k0 = chunk * 64;
        uint32_t sbase = sb + stage * STAGE_BYTES;
        uint32_t mb = stage ? mb1 : mb0;
        MBAR_EXPECT_TX(mb, (uint32_t)STAGE_BYTES);
        tma2d(sbase + OFF_AH, &tmAh, k0, brow, mb);
        tma2d(sbase + OFF_AL, &tmAl, k0, brow, mb);
        tma2d(sbase + OFF_BH, &tmWh, k0, wyoff + ncb, mb);
        tma2d(sbase + OFF_BL, &tmWl, k0, wyoff + ncb, mb);
    };

    if (tid == 0) load_chunk(0, 0);

    for (int chunk = 0; chunk < 4; chunk++) {
        int stage = chunk & 1;
        if (chunk < 3 && tid == 0) load_chunk(chunk + 1, stage ^ 1);
        MBAR_WAIT(stage ? mb1 : mb0, (chunk >> 1) & 1);

        uint32_t sbase = sb + stage * STAGE_BYTES;
        #pragma unroll
        for (int ks = 0; ks < 4; ks++) {
            uint32_t kb   = (uint32_t)(ks * 32 + ((lane >> 4) & 1) * 16);
            uint32_t kswz = kb ^ ((uint32_t)(lane & 7) << 4);
            uint32_t rsub = (uint32_t)((lane & 7) + ((lane >> 3) & 1) * 8);

            uint32_t adA = sbase + (wm + rsub) * 128 + kswz;
            uint32_t adB = sbase + (wn + rsub) * 128 + kswz;

            uint32_t a[4][4];                    // reused: hi then lo
            uint32_t bh[2][4], bl[2][4];
            #pragma unroll
            for (int mi = 0; mi < 4; mi++)
                ldsm_x4(a[mi], adA + OFF_AH + mi * 2048);
            #pragma unroll
            for (int nj = 0; nj < 2; nj++) {
                ldsm_x4(bh[nj], adB + OFF_BH + nj * 2048);
                ldsm_x4(bl[nj], adB + OFF_BL + nj * 2048);
            }
            #pragma unroll
            for (int mi = 0; mi < 4; mi++)
                #pragma unroll
                for (int ni = 0; ni < 4; ni++) {
                    int nj = ni >> 1, sel = ni & 1;
                    mma_bf16(acc[mi][ni], a[mi], bh[nj][sel], bh[nj][sel + 2]);
                    mma_bf16(acc[mi][ni], a[mi], bl[nj][sel], bl[nj][sel + 2]);
                }
            #pragma unroll
            for (int mi = 0; mi < 4; mi++)
                ldsm_x4(a[mi], adA + OFF_AL + mi * 2048);
            #pragma unroll
            for (int mi = 0; mi < 4; mi++)
                #pragma unroll
                for (int ni = 0; ni < 4; ni++) {
                    int nj = ni >> 1, sel = ni & 1;
                    mma_bf16(acc[mi][ni], a[mi], bh[nj][sel], bh[nj][sel + 2]);
                }
        }
        __syncthreads();
    }

    bool chalf = (ncb >= 256);
    int  cbase = chalf ? (ncb - 256) : ncb;
    #pragma unroll
    for (int mi = 0; mi < 4; mi++) {
        int row0 = brow + wm + mi * 16 + (lane >> 2);
        int row1 = row0 + 8;
        #pragma unroll
        for (int ni = 0; ni < 4; ni++) {
            int gcol = cbase + wn + ni * 8 + (lane & 3) * 2;
            float2 bb = *(const float2*)(bias + (chalf ? 256 : 0) + gcol);
            float2 v0, v1;
            v0.x = acc[mi][ni][0] + bb.x; v0.y = acc[mi][ni][1] + bb.y;
            v1.x = acc[mi][ni][2] + bb.x; v1.y = acc[mi][ni][3] + bb.y;
            if (!chalf) {
                if (row0 < M) *(float2*)(Bout + (size_t)row0 * 256 + gcol) = v0;
                if (row1 < M) *(float2*)(Bout + (size_t)row1 * 256 + gcol) = v1;
            } else {
                if (row0 < M) {
                    float di = dinv[row0];
                    *(float2*)(Cout + (size_t)row0 * 256 + gcol) = v0;
                    *(__half2*)(Yh + (size_t)row0 * 256 + gcol) =
                        __floats2half2_rn(di * v0.x, di * v0.y);
                }
                if (row1 < M) {
                    float di = dinv[row1];
                    *(float2*)(Cout + (size_t)row1 * 256 + gcol) = v1;
                    *(__half2*)(Yh + (size_t)row1 * 256 + gcol) =
                        __floats2half2_rn(di * v1.x, di * v1.y);
                }
            }
        }
    }
}

// ---------------- fused aggregate + mix + l2norm + relu -> bf16 hi/lo ------
// Vectorized gather: warp g handles neighbors j=g (mod 8); lane s loads 16B
// (8 halves) covering features s*8..s*8+7. 8x fewer LDGs than scalar.
__global__ __launch_bounds__(256)
void agg_combine_kernel(const float* __restrict__ Bm, const float* __restrict__ C,
                        const __half* __restrict__ Yh, int M)
{
    int i = blockIdx.x;
    int t = threadIdx.x;
    if (i >= M) return;

    int g = t >> 5;          // warp 0..7 = neighbor group
    int sl = t & 31;         // lane = feature chunk (8 halves)

    __shared__ int cols[256];
    __shared__ float sacc[8][256];
    __shared__ float wsum[8];

    int s = g_rowstart[i];
    int e = s + g_cnt[i];

    float facc[8];
    #pragma unroll
    for (int q = 0; q < 8; q++) facc[q] = 0.0f;

    for (int base = s; base < e; base += 256) {
        int m = min(256, e - base);
        if (t < m) cols[t] = g_colidx[base + t];
        __syncthreads();
        for (int j = g; j < m; j += 8) {
            const __half* yrow = Yh + (size_t)cols[j] * D_DIM + sl * 8;
            uint4 v = *reinterpret_cast<const uint4*>(yrow);
            const __half2* hp = reinterpret_cast<const __half2*>(&v);
            #pragma unroll
            for (int q = 0; q < 4; q++) {
                float2 f = __half22float2(hp[q]);
                facc[q * 2]     += f.x;
                facc[q * 2 + 1] += f.y;
            }
        }
        __syncthreads();
    }
    #pragma unroll
    for (int q = 0; q < 8; q++) sacc[g][sl * 8 + q] = facc[q];
    __syncthreads();

    float acc = 0.0f;
    #pragma unroll
    for (int g2 = 0; g2 < 8; g2++) acc += sacc[g2][t];

    float di = g_dinv[i];
    float nb = C[(size_t)i * D_DIM + t];
    float prop = di * acc + di * di * nb;
    float h = Bm[(size_t)i * D_DIM + t] + 0.5f * prop + 0.5f * nb;

    float v = h * h;
    #pragma unroll
    for (int o = 16; o > 0; o >>= 1)
        v += __shfl_xor_sync(0xffffffffu, v, o);
    if ((t & 31) == 0) wsum[t >> 5] = v;
    __syncthreads();
    float tot = 0.0f;
    #pragma unroll
    for (int w = 0; w < 8; w++) tot += wsum[w];
    float nrm = sqrtf(tot);
    h = fmaxf(h / fmaxf(nrm, 1e-12f), 0.0f);

    __nv_bfloat16 hi = __float2bfloat16(h);
    size_t off = (size_t)i * D_DIM + t;
    g_Ah[off] = hi;
    g_Al[off] = __float2bfloat16(h - __bfloat162float(hi));
}

// ---------------- output GEMM: Out[M,32] = (Hh+Hl) @ W2 + b2 ---------------
__global__ __launch_bounds__(256)
void gemm_out_kernel(const float* __restrict__ W2,
                     const float* __restrict__ b2, float* __restrict__ Out, int M)
{
    extern __shared__ __align__(16) float smem[];
    float* sW = smem;                 // [256][32] (32KB)
    float* sH = smem + D_DIM * 32;    // [32][256] (32KB)

    int tid  = threadIdx.x;
    int brow = blockIdx.x * 32;

    #pragma unroll
    for (int l = 0; l < 8; l++) {
        int idx = tid + l * 256;
        reinterpret_cast<float4*>(sW)[idx] = reinterpret_cast<const float4*>(W2)[idx];
    }
    #pragma unroll
    for (int l = 0; l < 16; l++) {
        int idx = tid + l * 256;       // bf16x2 index into 32x256 (4096 total)
        int r = idx >> 7, c2 = idx & 127;
        float2 f = make_float2(0.f, 0.f);
        if (brow + r < M) {
            size_t off = (size_t)(brow + r) * D_DIM + c2 * 2;
            __nv_bfloat162 hv = *(const __nv_bfloat162*)(g_Ah + off);
            __nv_bfloat162 lv = *(const __nv_bfloat162*)(g_Al + off);
            f.x = __bfloat162float(hv.x) + __bfloat162float(lv.x);
            f.y = __bfloat162float(hv.y) + __bfloat162float(lv.y);
        }
        *reinterpret_cast<float2*>(sH + r * D_DIM + c2 * 2) = f;
    }
    __syncthreads();

    int ry = tid >> 3;
    int c4 = (tid & 7) * 4;
    float4 acc = make_float4(0.f, 0.f, 0.f, 0.f);
    #pragma unroll 8
    for (int k = 0; k < D_DIM; k++) {
        float h = sH[ry * D_DIM + k];
        float4 w = *reinterpret_cast<const float4*>(&sW[k * 32 + c4]);
        acc.x = fmaf(h, w.x, acc.x);
        acc.y = fmaf(h, w.y, acc.y);
        acc.z = fmaf(h, w.z, acc.z);
        acc.w = fmaf(h, w.w, acc.w);
    }
    int grow = brow + ry;
    if (grow < M) {
        float4 bb = *reinterpret_cast<const float4*>(b2 + c4);
        acc.x += bb.x; acc.y += bb.y; acc.z += bb.z; acc.w += bb.w;
        *reinterpret_cast<float4*>(Out + (size_t)grow * O_DIM + c4) = acc;
    }
}

// ---------------- host launcher (single stream) ----------------------------
typedef CUresult (CUDAAPI *PFN_encTiled)(
    CUtensorMap*, CUtensorMapDataType, cuuint32_t, void*,
    const cuuint64_t*, const cuuint64_t*, const cuuint32_t*, const cuuint32_t*,
    CUtensorMapInterleave, CUtensorMapSwizzle, CUtensorMapL2promotion,
    CUtensorMapFloatOOBfill);

extern "C" void kernel_launch(void* const* d_in, const int* in_sizes, int n_in,
                              void* d_out, int out_size)
{
    const float* x   = (const float*)d_in[0];
    const int*   ei  = (const int*)  d_in[1];
    const float* W0  = (const float*)d_in[2];
    const float* b0  = (const float*)d_in[3];
    const float* Wn0 = (const float*)d_in[4];
    const float* bn0 = (const float*)d_in[5];
    const float* W1  = (const float*)d_in[6];
    const float* b1  = (const float*)d_in[7];
    const float* Wn1 = (const float*)d_in[8];
    const float* bn1 = (const float*)d_in[9];
    const float* W2  = (const float*)d_in[10];
    const float* b2  = (const float*)d_in[11];

    int M = in_sizes[0] / D_DIM;
    int E = in_sizes[1] / 2;
    const int* erow = ei;
    const int* ecol = ei + E;

    float *pB, *pC, *pBiasC, *pDinv;
    __half* pYh;
    __nv_bfloat16 *pAh, *pAl, *pWh, *pWl;
    int *pCnt, *pBase;
    cudaGetSymbolAddress((void**)&pB,    g_B);
    cudaGetSymbolAddress((void**)&pC,    g_C);
    cudaGetSymbolAddress((void**)&pYh,   g_Yh);
    cudaGetSymbolAddress((void**)&pDinv, g_dinv);
    cudaGetSymbolAddress((void**)&pAh,   g_Ah);
    cudaGetSymbolAddress((void**)&pAl,   g_Al);
    cudaGetSymbolAddress((void**)&pWh,   g_Wh);
    cudaGetSymbolAddress((void**)&pWl,   g_Wl);
    cudaGetSymbolAddress((void**)&pBiasC, g_biasC);
    cudaGetSymbolAddress((void**)&pCnt,  g_cnt);
    cudaGetSymbolAddress((void**)&pBase, g_base);

    static CUtensorMap tmAh, tmAl, tmWh, tmWl;
    static bool init_done = false;
    if (!init_done) {
        cudaFuncSetAttribute(hmma_gemm_kernel,
                             cudaFuncAttributeMaxDynamicSharedMemorySize,
                             2 * STAGE_BYTES + 1024);
        cudaFuncSetAttribute(gemm_out_kernel,
                             cudaFuncAttributeMaxDynamicSharedMemorySize, 65536);

        void* fp = nullptr;
        cudaDriverEntryPointQueryResult qr;
#if CUDART_VERSION >= 12050
        cudaGetDriverEntryPointByVersion("cuTensorMapEncodeTiled", &fp, 12000,
                                         cudaEnableDefault, &qr);
#else
        cudaGetDriverEntryPoint("cuTensorMapEncodeTiled", &fp,
                                cudaEnableDefault, &qr);
#endif
        PFN_encTiled enc = (PFN_encTiled)fp;

        cuuint64_t dimsA[2] = {256, (cuuint64_t)M};
        cuuint64_t strA[1]  = {256 * 2};
        cuuint64_t dimsW[2] = {256, 1024};
        cuuint64_t strW[1]  = {256 * 2};
        cuuint32_t box[2]   = {64, 128};
        cuuint32_t estr[2]  = {1, 1};
        enc(&tmAh, CU_TENSOR_MAP_DATA_TYPE_BFLOAT16, 2, pAh, dimsA, strA, box,
            estr, CU_TENSOR_MAP_INTERLEAVE_NONE, CU_TENSOR_MAP_SWIZZLE_128B,
            CU_TENSOR_MAP_L2_PROMOTION_L2_128B, CU_TENSOR_MAP_FLOAT_OOB_FILL_NONE);
        enc(&tmAl, CU_TENSOR_MAP_DATA_TYPE_BFLOAT16, 2, pAl, dimsA, strA, box,
            estr, CU_TENSOR_MAP_INTERLEAVE_NONE, CU_TENSOR_MAP_SWIZZLE_128B,
            CU_TENSOR_MAP_L2_PROMOTION_L2_128B, CU_TENSOR_MAP_FLOAT_OOB_FILL_NONE);
        enc(&tmWh, CU_TENSOR_MAP_DATA_TYPE_BFLOAT16, 2, pWh, dimsW, strW, box,
            estr, CU_TENSOR_MAP_INTERLEAVE_NONE, CU_TENSOR_MAP_SWIZZLE_128B,
            CU_TENSOR_MAP_L2_PROMOTION_L2_128B, CU_TENSOR_MAP_FLOAT_OOB_FILL_NONE);
        enc(&tmWl, CU_TENSOR_MAP_DATA_TYPE_BFLOAT16, 2, pWl, dimsW, strW, box,
            estr, CU_TENSOR_MAP_INTERLEAVE_NONE, CU_TENSOR_MAP_SWIZZLE_128B,
            CU_TENSOR_MAP_L2_PROMOTION_L2_128B, CU_TENSOR_MAP_FLOAT_OOB_FILL_NONE);
        init_done = true;
    }

    int eb = (E + 255) / 256;
    int nb = (M + 255) / 256;
    dim3 gg((M + 127) / 128, 4);
    dim3 fgrid(257, 2, 2);
    dim3 pgrid(8, 16, 2), pblk(32, 8);

    // CSR build + dinv (before GEMM: its epilogue reads dinv)
    cudaMemsetAsync(pCnt, 0, (size_t)M * sizeof(int));
    cudaMemsetAsync(pBase, 0, sizeof(int));
    count_edges_kernel<<<eb, 256>>>(erow, E);
    offsets_kernel<<<nb, 256>>>(M);
    fill_csr_kernel<<<eb, 256>>>(erow, ecol, E);

    // weight prep (both layers, one launch each)
    fuse_wb_kernel<<<fgrid, 256>>>(W0, Wn0, b0, bn0, W1, Wn1, b1, bn1);
    pack_w_kernel<<<pgrid, pblk>>>(W0, b0, W1, b1);

    // split input
    split_kernel<<<(M * D_DIM / 4 + 255) / 256, 256>>>(x, M * D_DIM / 4);

    // layer 1
    hmma_gemm_kernel<<<gg, 256, 2 * STAGE_BYTES + 1024>>>(
        tmAh, tmAl, tmWh, tmWl, 0, pBiasC, pB, pC, pYh, pDinv, M);
    agg_combine_kernel<<<M, 256>>>(pB, pC, pYh, M);

    // layer 2
    hmma_gemm_kernel<<<gg, 256, 2 * STAGE_BYTES + 1024>>>(
        tmAh, tmAl, tmWh, tmWl, 512, pBiasC + 512, pB, pC, pYh, pDinv, M);
    agg_combine_kernel<<<M, 256>>>(pB, pC, pYh, M);

    // output layer
    gemm_out_kernel<<<(M + 31) / 32, 256, 65536>>>(W2, b2, (float*)d_out, M);
}

// round 14
// speedup vs baseline: 1.5250x; 1.0063x over previous
#include <cuda_runtime.h>
#include <cuda.h>
#include <cuda_bf16.h>
#include <cuda_fp16.h>
#include <math.h>
#include <stdint.h>

#define D_DIM 256
#define O_DIM 32
#define NMAX 50000
#define EMAX 800000

// ---------------- scratch (static device globals; no runtime allocation) ---
__device__ float g_B[(size_t)NMAX * D_DIM];   // h1 = A@W+b
__device__ float g_C[(size_t)NMAX * D_DIM];   // nb  (fused weights)
__device__ __align__(1024) __half g_Yh[(size_t)NMAX * D_DIM]; // dinv*nb fp16
__device__ __align__(1024) __nv_bfloat16 g_Ah[(size_t)NMAX * D_DIM]; // input hi
__device__ __align__(1024) __nv_bfloat16 g_Al[(size_t)NMAX * D_DIM]; // input lo
__device__ __align__(1024) __nv_bfloat16 g_Wh[2][512 * 256];  // weights [n][k] hi
__device__ __align__(1024) __nv_bfloat16 g_Wl[2][512 * 256];  // weights [n][k] lo
__device__ float g_biasC[2][512];
__device__ float g_WfP[2][2][256 * 256];      // partial W@Wn (layer, k-half)
__device__ float g_bfP[2][2][256];            // partial b@Wn + bn
__device__ float g_dinv[NMAX];
__device__ int   g_cnt[NMAX];
__device__ int   g_rowstart[NMAX];
__device__ int   g_cursor[NMAX];
__device__ int   g_colidx[EMAX];
__device__ int   g_base;                      // global slot cursor

// ================= helpers =================================================
__device__ __forceinline__ uint32_t smem_u32(const void* p) {
    uint32_t a;
    asm("{ .reg .u64 t; cvta.to.shared.u64 t, %1; cvt.u32.u64 %0, t; }"
        : "=r"(a) : "l"(p));
    return a;
}
__device__ __forceinline__ void ldsm_x4(uint32_t* r, uint32_t addr) {
    asm volatile("ldmatrix.sync.aligned.m8n8.x4.shared.b16 {%0,%1,%2,%3}, [%4];"
                 : "=r"(r[0]), "=r"(r[1]), "=r"(r[2]), "=r"(r[3]) : "r"(addr));
}
__device__ __forceinline__ void mma_bf16(float* c, const uint32_t* a,
                                         uint32_t b0, uint32_t b1) {
    asm volatile(
        "mma.sync.aligned.m16n8k16.row.col.f32.bf16.bf16.f32 "
        "{%0,%1,%2,%3}, {%4,%5,%6,%7}, {%8,%9}, {%0,%1,%2,%3};"
        : "+f"(c[0]), "+f"(c[1]), "+f"(c[2]), "+f"(c[3])
        : "r"(a[0]), "r"(a[1]), "r"(a[2]), "r"(a[3]), "r"(b0), "r"(b1));
}
__device__ __forceinline__ void tma2d(uint32_t smem, const CUtensorMap* map,
                                      int x, int y, uint32_t mbar) {
    asm volatile(
        "cp.async.bulk.tensor.2d.shared::cta.global.tile.mbarrier::complete_tx::bytes "
        "[%0], [%1, {%2, %3}], [%4];"
        :: "r"(smem), "l"(map), "r"(x), "r"(y), "r"(mbar) : "memory");
}
#define MBAR_INIT(mb, c)  asm volatile("mbarrier.init.shared.b64 [%0], %1;" :: "r"(mb), "r"(c) : "memory")
#define MBAR_EXPECT_TX(mb, tx) asm volatile("mbarrier.arrive.expect_tx.shared.b64 _, [%0], %1;" :: "r"(mb), "r"(tx) : "memory")
#define MBAR_WAIT(mb, par) do {                                              \
    uint32_t _mb = (mb), _p = (par), _done;                                  \
    asm volatile("{\n\t.reg .pred p;\n\t"                                    \
        "mbarrier.try_wait.parity.acquire.cta.shared::cta.b64 p, [%1], %2;\n\t" \
        "selp.b32 %0, 1, 0, p;\n\t}" : "=r"(_done) : "r"(_mb), "r"(_p) : "memory"); \
    if (!_done) {                                                            \
        asm volatile("{\n\t.reg .pred P1;\n\t"                               \
            "WL_%=:\n\t"                                                     \
            "mbarrier.try_wait.parity.acquire.cta.shared::cta.b64 P1, [%0], %1, 0x989680;\n\t" \
            "@P1 bra.uni WD_%=;\n\tbra.uni WL_%=;\n\tWD_%=:\n\t}"            \
            :: "r"(_mb), "r"(_p) : "memory");                                \
    }                                                                        \
} while (0)
#define SW128(off) ((off) ^ (((off) >> 3) & 0x70))

// ---------------- CSR build (scan-free) ------------------------------------
__global__ void count_edges_kernel(const int* __restrict__ row, int e) {
    int i = blockIdx.x * blockDim.x + threadIdx.x;
    if (i < e) atomicAdd(&g_cnt[row[i]], 1);
}
__global__ void offsets_kernel(int n) {
    int i = blockIdx.x * blockDim.x + threadIdx.x;
    int lane = threadIdx.x & 31;
    int c = (i < n) ? g_cnt[i] : 0;
    int incl = c;
    #pragma unroll
    for (int o = 1; o < 32; o <<= 1) {
        int v = __shfl_up_sync(0xffffffffu, incl, o);
        if (lane >= o) incl += v;
    }
    int total = __shfl_sync(0xffffffffu, incl, 31);
    int base = 0;
    if (lane == 31 && total > 0) base = atomicAdd(&g_base, total);
    base = __shfl_sync(0xffffffffu, base, 31);
    if (i < n) {
        int start = base + incl - c;
        g_rowstart[i] = start;
        g_cursor[i]   = start;
        g_dinv[i]     = rsqrtf((float)(c + 1));
    }
}
__global__ void fill_csr_kernel(const int* __restrict__ row,
                                const int* __restrict__ col, int e) {
    int i = blockIdx.x * blockDim.x + threadIdx.x;
    if (i < e) {
        int p = atomicAdd(&g_cursor[row[i]], 1);
        g_colidx[p] = col[i];
    }
}

// ---------------- weight prep (both layers, k-split x2 in one launch) ------
__global__ void fuse_wb_kernel(const float* __restrict__ W0,
                               const float* __restrict__ Wn0,
                               const float* __restrict__ b0,
                               const float* __restrict__ bn0,
                               const float* __restrict__ W1,
                               const float* __restrict__ Wn1,
                               const float* __restrict__ b1,
                               const float* __restrict__ bn1) {
    int layer = blockIdx.y, part = blockIdx.z;
    const float* W  = layer ? W1  : W0;
    const float* Wn = layer ? Wn1 : Wn0;
    const float* b  = layer ? b1  : b0;
    const float* bn = layer ? bn1 : bn0;
    int n = threadIdx.x;
    int kb = blockIdx.x;
    int j0 = part * 128;
    if (kb < 256) {
        const float* wrow = W + kb * 256 + j0;
        const float* wncol = Wn + (size_t)j0 * 256 + n;
        float acc = 0.0f;
        #pragma unroll 8
        for (int j = 0; j < 128; j++)
            acc = fmaf(__ldg(wrow + j), wncol[j * 256], acc);
        g_WfP[layer][part][kb * 256 + n] = acc;
    } else {
        float acc = (part == 0) ? bn[n] : 0.0f;
        #pragma unroll 8
        for (int j = 0; j < 128; j++)
            acc = fmaf(__ldg(b + j0 + j), Wn[(size_t)(j0 + j) * 256 + n], acc);
        g_bfP[layer][part][n] = acc;
    }
}
__global__ void pack_w_kernel(const float* __restrict__ W0,
                              const float* __restrict__ b0,
                              const float* __restrict__ W1,
                              const float* __restrict__ b1) {
    __shared__ float s[32][33];
    int layer = blockIdx.z;
    const float* W = layer ? W1 : W0;
    const float* b = layer ? b1 : b0;
    int k0 = blockIdx.x * 32, n0 = blockIdx.y * 32;
    int tx = threadIdx.x, ty = threadIdx.y;
    #pragma unroll
    for (int i = 0; i < 4; i++) {
        int k = k0 + ty + i * 8;
        float v;
        if (n0 < 256) v = W[k * 256 + n0 + tx];
        else {
            int idx = k * 256 + (n0 - 256) + tx;
            v = g_WfP[layer][0][idx] + g_WfP[layer][1][idx];
        }
        s[ty + i * 8][tx] = v;
    }
    __syncthreads();
    #pragma unroll
    for (int i = 0; i < 4; i++) {
        int n = n0 + ty + i * 8;
        float w = s[tx][ty + i * 8];
        __nv_bfloat16 hi = __float2bfloat16(w);
        g_Wh[layer][n * 256 + k0 + tx] = hi;
        g_Wl[layer][n * 256 + k0 + tx] = __float2bfloat16(w - __bfloat162float(hi));
    }
    if (blockIdx.x == 0 && tx == 0) {
        #pragma unroll
        for (int i = 0; i < 4; i++) {
            int n = n0 + ty + i * 8;
            g_biasC[layer][n] = (n < 256) ? b[n]
                : (g_bfP[layer][0][n - 256] + g_bfP[layer][1][n - 256]);
        }
    }
}
__global__ void split_kernel(const float* __restrict__ x, int total4) {
    int i = blockIdx.x * blockDim.x + threadIdx.x;
    if (i < total4) {
        float4 v = reinterpret_cast<const float4*>(x)[i];
        __nv_bfloat16 h0 = __float2bfloat16(v.x), h1 = __float2bfloat16(v.y);
        __nv_bfloat16 h2 = __float2bfloat16(v.z), h3 = __float2bfloat16(v.w);
        __nv_bfloat162 hA, hB, lA, lB;
        hA.x = h0; hA.y = h1; hB.x = h2; hB.y = h3;
        lA.x = __float2bfloat16(v.x - __bfloat162float(h0));
        lA.y = __float2bfloat16(v.y - __bfloat162float(h1));
        lB.x = __float2bfloat16(v.z - __bfloat162float(h2));
        lB.y = __float2bfloat16(v.w - __bfloat162float(h3));
        reinterpret_cast<__nv_bfloat162*>(g_Ah)[i * 2]     = hA;
        reinterpret_cast<__nv_bfloat162*>(g_Ah)[i * 2 + 1] = hB;
        reinterpret_cast<__nv_bfloat162*>(g_Al)[i * 2]     = lA;
        reinterpret_cast<__nv_bfloat162*>(g_Al)[i * 2 + 1] = lB;
    }
}

// ---------------- HMMA GEMM: [B|C] = A @ Wcomb, split-bf16 x3, TMA loads ---
// 512 threads, 16 warps in 4x4 grid, warp tile 32x32 -> 4 warps/SMSP to
// feed the tensor pipe (R6 profile: 50.8% tensor-busy at 2 warps/SMSP).
#define STAGE_BYTES 65536
__global__ __launch_bounds__(512)
void hmma_gemm_kernel(const __grid_constant__ CUtensorMap tmAh,
                      const __grid_constant__ CUtensorMap tmAl,
                      const __grid_constant__ CUtensorMap tmWh,
                      const __grid_constant__ CUtensorMap tmWl,
                      int wyoff,
                      const float* __restrict__ bias,
                      float* __restrict__ Bout, float* __restrict__ Cout,
                      __half* __restrict__ Yh, const float* __restrict__ dinv,
                      int M)
{
    extern __shared__ char dsm_raw[];
    __shared__ __align__(8) unsigned long long s_mbar[2];
    uint32_t dynu = smem_u32(dsm_raw);
    uint32_t pad = ((dynu + 1023) & ~1023u) - dynu;
    uint32_t sb = dynu + pad;
    const uint32_t OFF_AH = 0, OFF_AL = 16384, OFF_BH = 32768, OFF_BL = 49152;

    int tid  = threadIdx.x;
    int warp = tid >> 5, lane = tid & 31;
    int brow = blockIdx.x * 128;
    int ncb  = blockIdx.y * 128;
    int wm   = (warp >> 2) * 32;    // 4 row groups of 32
    int wn   = (warp & 3) * 32;     // 4 col groups of 32

    uint32_t mb0 = smem_u32(&s_mbar[0]);
    uint32_t mb1 = smem_u32(&s_mbar[1]);
    if (tid == 0) { MBAR_INIT(mb0, 1); MBAR_INIT(mb1, 1); }
    __syncthreads();

    float acc[2][4][4];
    #pragma unroll
    for (int mi = 0; mi < 2; mi++)
        #pragma unroll
        for (int ni = 0; ni < 4; ni++)
            #pragma unroll
            for (int q = 0; q < 4; q++) acc[mi][ni][q] = 0.0f;

    auto load_chunk = [&](int chunk, int stage) {
        int k0 = chunk * 64;
        uint32_t sbase = sb + stage * STAGE_BYTES;
        uint32_t mb = stage ? mb1 : mb0;
        MBAR_EXPECT_TX(mb, (uint32_t)STAGE_BYTES);
        tma2d(sbase + OFF_AH, &tmAh, k0, brow, mb);
        tma2d(sbase + OFF_AL, &tmAl, k0, brow, mb);
        tma2d(sbase + OFF_BH, &tmWh, k0, wyoff + ncb, mb);
        tma2d(sbase + OFF_BL, &tmWl, k0, wyoff + ncb, mb);
    };

    if (tid == 0) load_chunk(0, 0);

    for (int chunk = 0; chunk < 4; chunk++) {
        int stage = chunk & 1;
        if (chunk < 3 && tid == 0) load_chunk(chunk + 1, stage ^ 1);
        MBAR_WAIT(stage ? mb1 : mb0, (chunk >> 1) & 1);

        uint32_t sbase = sb + stage * STAGE_BYTES;
        #pragma unroll
        for (int ks = 0; ks < 4; ks++) {
            uint32_t kb   = (uint32_t)(ks * 32 + ((lane >> 4) & 1) * 16);
            uint32_t kswz = kb ^ ((uint32_t)(lane & 7) << 4);
            uint32_t rsub = (uint32_t)((lane & 7) + ((lane >> 3) & 1) * 8);

            uint32_t adA = sbase + (wm + rsub) * 128 + kswz;
            uint32_t adB = sbase + (wn + rsub) * 128 + kswz;

            uint32_t a[2][4];                    // reused: hi then lo
            uint32_t bh[2][4], bl[2][4];
            #pragma unroll
            for (int mi = 0; mi < 2; mi++)
                ldsm_x4(a[mi], adA + OFF_AH + mi * 2048);
            #pragma unroll
            for (int nj = 0; nj < 2; nj++) {
                ldsm_x4(bh[nj], adB + OFF_BH + nj * 2048);
                ldsm_x4(bl[nj], adB + OFF_BL + nj * 2048);
            }
            #pragma unroll
            for (int mi = 0; mi < 2; mi++)
                #pragma unroll
                for (int ni = 0; ni < 4; ni++) {
                    int nj = ni >> 1, sel = ni & 1;
                    mma_bf16(acc[mi][ni], a[mi], bh[nj][sel], bh[nj][sel + 2]);
                    mma_bf16(acc[mi][ni], a[mi], bl[nj][sel], bl[nj][sel + 2]);
                }
            #pragma unroll
            for (int mi = 0; mi < 2; mi++)
                ldsm_x4(a[mi], adA + OFF_AL + mi * 2048);
            #pragma unroll
            for (int mi = 0; mi < 2; mi++)
                #pragma unroll
                for (int ni = 0; ni < 4; ni++) {
                    int nj = ni >> 1, sel = ni & 1;
                    mma_bf16(acc[mi][ni], a[mi], bh[nj][sel], bh[nj][sel + 2]);
                }
        }
        __syncthreads();
    }

    bool chalf = (ncb >= 256);
    int  cbase = chalf ? (ncb - 256) : ncb;
    #pragma unroll
    for (int mi = 0; mi < 2; mi++) {
        int row0 = brow + wm + mi * 16 + (lane >> 2);
        int row1 = row0 + 8;
        #pragma unroll
        for (int ni = 0; ni < 4; ni++) {
            int gcol = cbase + wn + ni * 8 + (lane & 3) * 2;
            float2 bb = *(const float2*)(bias + (chalf ? 256 : 0) + gcol);
            float2 v0, v1;
            v0.x = acc[mi][ni][0] + bb.x; v0.y = acc[mi][ni][1] + bb.y;
            v1.x = acc[mi][ni][2] + bb.x; v1.y = acc[mi][ni][3] + bb.y;
            if (!chalf) {
                if (row0 < M) *(float2*)(Bout + (size_t)row0 * 256 + gcol) = v0;
                if (row1 < M) *(float2*)(Bout + (size_t)row1 * 256 + gcol) = v1;
            } else {
                if (row0 < M) {
                    float di = dinv[row0];
                    *(float2*)(Cout + (size_t)row0 * 256 + gcol) = v0;
                    *(__half2*)(Yh + (size_t)row0 * 256 + gcol) =
                        __floats2half2_rn(di * v0.x, di * v0.y);
                }
                if (row1 < M) {
                    float di = dinv[row1];
                    *(float2*)(Cout + (size_t)row1 * 256 + gcol) = v1;
                    *(__half2*)(Yh + (size_t)row1 * 256 + gcol) =
                        __floats2half2_rn(di * v1.x, di * v1.y);
                }
            }
        }
    }
}

// ---------------- fused aggregate + mix + l2norm + relu -> bf16 hi/lo ------
// Vectorized gather: warp g handles neighbors j=g (mod 8); lane s loads 16B
// (8 halves) covering features s*8..s*8+7.
__global__ __launch_bounds__(256)
void agg_combine_kernel(const float* __restrict__ Bm, const float* __restrict__ C,
                        const __half* __restrict__ Yh, int M)
{
    int i = blockIdx.x;
    int t = threadIdx.x;
    if (i >= M) return;

    int g = t >> 5;          // warp 0..7 = neighbor group
    int sl = t & 31;         // lane = feature chunk (8 halves)

    __shared__ int cols[256];
    __shared__ float sacc[8][256];
    __shared__ float wsum[8];

    int s = g_rowstart[i];
    int e = s + g_cnt[i];

    float facc[8];
    #pragma unroll
    for (int q = 0; q < 8; q++) facc[q] = 0.0f;

    for (int base = s; base < e; base += 256) {
        int m = min(256, e - base);
        if (t < m) cols[t] = g_colidx[base + t];
        __syncthreads();
        for (int j = g; j < m; j += 8) {
            const __half* yrow = Yh + (size_t)cols[j] * D_DIM + sl * 8;
            uint4 v = *reinterpret_cast<const uint4*>(yrow);
            const __half2* hp = reinterpret_cast<const __half2*>(&v);
            #pragma unroll
            for (int q = 0; q < 4; q++) {
                float2 f = __half22float2(hp[q]);
                facc[q * 2]     += f.x;
                facc[q * 2 + 1] += f.y;
            }
        }
        __syncthreads();
    }
    #pragma unroll
    for (int q = 0; q < 8; q++) sacc[g][sl * 8 + q] = facc[q];
    __syncthreads();

    float acc = 0.0f;
    #pragma unroll
    for (int g2 = 0; g2 < 8; g2++) acc += sacc[g2][t];

    float di = g_dinv[i];
    float nb = C[(size_t)i * D_DIM + t];
    float prop = di * acc + di * di * nb;
    float h = Bm[(size_t)i * D_DIM + t] + 0.5f * prop + 0.5f * nb;

    float v = h * h;
    #pragma unroll
    for (int o = 16; o > 0; o >>= 1)
        v += __shfl_xor_sync(0xffffffffu, v, o);
    if ((t & 31) == 0) wsum[t >> 5] = v;
    __syncthreads();
    float tot = 0.0f;
    #pragma unroll
    for (int w = 0; w < 8; w++) tot += wsum[w];
    float nrm = sqrtf(tot);
    h = fmaxf(h / fmaxf(nrm, 1e-12f), 0.0f);

    __nv_bfloat16 hi = __float2bfloat16(h);
    size_t off = (size_t)i * D_DIM + t;
    g_Ah[off] = hi;
    g_Al[off] = __float2bfloat16(h - __bfloat162float(hi));
}

// ---------------- output GEMM: Out[M,32] = (Hh+Hl) @ W2 + b2 ---------------
__global__ __launch_bounds__(256)
void gemm_out_kernel(const float* __restrict__ W2,
                     const float* __restrict__ b2, float* __restrict__ Out, int M)
{
    extern __shared__ __align__(16) float smem[];
    float* sW = smem;                 // [256][32] (32KB)
    float* sH = smem + D_DIM * 32;    // [32][256] (32KB)

    int tid  = threadIdx.x;
    int brow = blockIdx.x * 32;

    #pragma unroll
    for (int l = 0; l < 8; l++) {
        int idx = tid + l * 256;
        reinterpret_cast<float4*>(sW)[idx] = reinterpret_cast<const float4*>(W2)[idx];
    }
    #pragma unroll
    for (int l = 0; l < 16; l++) {
        int idx = tid + l * 256;       // bf16x2 index into 32x256 (4096 total)
        int r = idx >> 7, c2 = idx & 127;
        float2 f = make_float2(0.f, 0.f);
        if (brow + r < M) {
            size_t off = (size_t)(brow + r) * D_DIM + c2 * 2;
            __nv_bfloat162 hv = *(const __nv_bfloat162*)(g_Ah + off);
            __nv_bfloat162 lv = *(const __nv_bfloat162*)(g_Al + off);
            f.x = __bfloat162float(hv.x) + __bfloat162float(lv.x);
            f.y = __bfloat162float(hv.y) + __bfloat162float(lv.y);
        }
        *reinterpret_cast<float2*>(sH + r * D_DIM + c2 * 2) = f;
    }
    __syncthreads();

    int ry = tid >> 3;
    int c4 = (tid & 7) * 4;
    float4 acc = make_float4(0.f, 0.f, 0.f, 0.f);
    #pragma unroll 8
    for (int k = 0; k < D_DIM; k++) {
        float h = sH[ry * D_DIM + k];
        float4 w = *reinterpret_cast<const float4*>(&sW[k * 32 + c4]);
        acc.x = fmaf(h, w.x, acc.x);
        acc.y = fmaf(h, w.y, acc.y);
        acc.z = fmaf(h, w.z, acc.z);
        acc.w = fmaf(h, w.w, acc.w);
    }
    int grow = brow + ry;
    if (grow < M) {
        float4 bb = *reinterpret_cast<const float4*>(b2 + c4);
        acc.x += bb.x; acc.y += bb.y; acc.z += bb.z; acc.w += bb.w;
        *reinterpret_cast<float4*>(Out + (size_t)grow * O_DIM + c4) = acc;
    }
}

// ---------------- host launcher (single stream) ----------------------------
typedef CUresult (CUDAAPI *PFN_encTiled)(
    CUtensorMap*, CUtensorMapDataType, cuuint32_t, void*,
    const cuuint64_t*, const cuuint64_t*, const cuuint32_t*, const cuuint32_t*,
    CUtensorMapInterleave, CUtensorMapSwizzle, CUtensorMapL2promotion,
    CUtensorMapFloatOOBfill);

extern "C" void kernel_launch(void* const* d_in, const int* in_sizes, int n_in,
                              void* d_out, int out_size)
{
    const float* x   = (const float*)d_in[0];
    const int*   ei  = (const int*)  d_in[1];
    const float* W0  = (const float*)d_in[2];
    const float* b0  = (const float*)d_in[3];
    const float* Wn0 = (const float*)d_in[4];
    const float* bn0 = (const float*)d_in[5];
    const float* W1  = (const float*)d_in[6];
    const float* b1  = (const float*)d_in[7];
    const float* Wn1 = (const float*)d_in[8];
    const float* bn1 = (const float*)d_in[9];
    const float* W2  = (const float*)d_in[10];
    const float* b2  = (const float*)d_in[11];

    int M = in_sizes[0] / D_DIM;
    int E = in_sizes[1] / 2;
    const int* erow = ei;
    const int* ecol = ei + E;

    float *pB, *pC, *pBiasC, *pDinv;
    __half* pYh;
    __nv_bfloat16 *pAh, *pAl, *pWh, *pWl;
    int *pCnt, *pBase;
    cudaGetSymbolAddress((void**)&pB,    g_B);
    cudaGetSymbolAddress((void**)&pC,    g_C);
    cudaGetSymbolAddress((void**)&pYh,   g_Yh);
    cudaGetSymbolAddress((void**)&pDinv, g_dinv);
    cudaGetSymbolAddress((void**)&pAh,   g_Ah);
    cudaGetSymbolAddress((void**)&pAl,   g_Al);
    cudaGetSymbolAddress((void**)&pWh,   g_Wh);
    cudaGetSymbolAddress((void**)&pWl,   g_Wl);
    cudaGetSymbolAddress((void**)&pBiasC, g_biasC);
    cudaGetSymbolAddress((void**)&pCnt,  g_cnt);
    cudaGetSymbolAddress((void**)&pBase, g_base);

    static CUtensorMap tmAh, tmAl, tmWh, tmWl;
    static bool init_done = false;
    if (!init_done) {
        cudaFuncSetAttribute(hmma_gemm_kernel,
                             cudaFuncAttributeMaxDynamicSharedMemorySize,
                             2 * STAGE_BYTES + 1024);
        cudaFuncSetAttribute(gemm_out_kernel,
                             cudaFuncAttributeMaxDynamicSharedMemorySize, 65536);

        void* fp = nullptr;
        cudaDriverEntryPointQueryResult qr;
#if CUDART_VERSION >= 12050
        cudaGetDriverEntryPointByVersion("cuTensorMapEncodeTiled", &fp, 12000,
                                         cudaEnableDefault, &qr);
#else
        cudaGetDriverEntryPoint("cuTensorMapEncodeTiled", &fp,
                                cudaEnableDefault, &qr);
#endif
        PFN_encTiled enc = (PFN_encTiled)fp;

        cuuint64_t dimsA[2] = {256, (cuuint64_t)M};
        cuuint64_t strA[1]  = {256 * 2};
        cuuint64_t dimsW[2] = {256, 1024};
        cuuint64_t strW[1]  = {256 * 2};
        cuuint32_t box[2]   = {64, 128};
        cuuint32_t estr[2]  = {1, 1};
        enc(&tmAh, CU_TENSOR_MAP_DATA_TYPE_BFLOAT16, 2, pAh, dimsA, strA, box,
            estr, CU_TENSOR_MAP_INTERLEAVE_NONE, CU_TENSOR_MAP_SWIZZLE_128B,
            CU_TENSOR_MAP_L2_PROMOTION_L2_128B, CU_TENSOR_MAP_FLOAT_OOB_FILL_NONE);
        enc(&tmAl, CU_TENSOR_MAP_DATA_TYPE_BFLOAT16, 2, pAl, dimsA, strA, box,
            estr, CU_TENSOR_MAP_INTERLEAVE_NONE, CU_TENSOR_MAP_SWIZZLE_128B,
            CU_TENSOR_MAP_L2_PROMOTION_L2_128B, CU_TENSOR_MAP_FLOAT_OOB_FILL_NONE);
        enc(&tmWh, CU_TENSOR_MAP_DATA_TYPE_BFLOAT16, 2, pWh, dimsW, strW, box,
            estr, CU_TENSOR_MAP_INTERLEAVE_NONE, CU_TENSOR_MAP_SWIZZLE_128B,
            CU_TENSOR_MAP_L2_PROMOTION_L2_128B, CU_TENSOR_MAP_FLOAT_OOB_FILL_NONE);
        enc(&tmWl, CU_TENSOR_MAP_DATA_TYPE_BFLOAT16, 2, pWl, dimsW, strW, box,
            estr, CU_TENSOR_MAP_INTERLEAVE_NONE, CU_TENSOR_MAP_SWIZZLE_128B,
            CU_TENSOR_MAP_L2_PROMOTION_L2_128B, CU_TENSOR_MAP_FLOAT_OOB_FILL_NONE);
        init_done = true;
    }

    int eb = (E + 255) / 256;
    int nb = (M + 255) / 256;
    dim3 gg((M + 127) / 128, 4);
    dim3 fgrid(257, 2, 2);
    dim3 pgrid(8, 16, 2), pblk(32, 8);

    // CSR build + dinv (before GEMM: its epilogue reads dinv)
    cudaMemsetAsync(pCnt, 0, (size_t)M * sizeof(int));
    cudaMemsetAsync(pBase, 0, sizeof(int));
    count_edges_kernel<<<eb, 256>>>(erow, E);
    offsets_kernel<<<nb, 256>>>(M);
    fill_csr_kernel<<<eb, 256>>>(erow, ecol, E);

    // weight prep (both layers, one launch each)
    fuse_wb_kernel<<<fgrid, 256>>>(W0, Wn0, b0, bn0, W1, Wn1, b1, bn1);
    pack_w_kernel<<<pgrid, pblk>>>(W0, b0, W1, b1);

    // split input
    split_kernel<<<(M * D_DIM / 4 + 255) / 256, 256>>>(x, M * D_DIM / 4);

    // layer 1
    hmma_gemm_kernel<<<gg, 512, 2 * STAGE_BYTES + 1024>>>(
        tmAh, tmAl, tmWh, tmWl, 0, pBiasC, pB, pC, pYh, pDinv, M);
    agg_combine_kernel<<<M, 256>>>(pB, pC, pYh, M);

    // layer 2
    hmma_gemm_kernel<<<gg, 512, 2 * STAGE_BYTES + 1024>>>(
        tmAh, tmAl, tmWh, tmWl, 512, pBiasC + 512, pB, pC, pYh, pDinv, M);
    agg_combine_kernel<<<M, 256>>>(pB, pC, pYh, M);

    // output layer
    gemm_out_kernel<<<(M + 31) / 32, 256, 65536>>>(W2, b2, (float*)d_out, M);
}

// round 15
// speedup vs baseline: 1.5332x; 1.0054x over previous
#include <cuda_runtime.h>
#include <cuda.h>
#include <cuda_bf16.h>
#include <cuda_fp16.h>
#include <math.h>
#include <stdint.h>

#define D_DIM 256
#define O_DIM 32
#define NMAX 50000
#define EMAX 800000

// ---------------- scratch (static device globals; no runtime allocation) ---
__device__ float g_B[(size_t)NMAX * D_DIM];   // h1 = A@W+b
__device__ float g_C[(size_t)NMAX * D_DIM];   // nb  (fused weights)
__device__ __align__(1024) __half g_Yh[(size_t)NMAX * D_DIM]; // dinv*nb fp16
__device__ __align__(1024) __nv_bfloat16 g_Ah[(size_t)NMAX * D_DIM]; // input hi
__device__ __align__(1024) __nv_bfloat16 g_Al[(size_t)NMAX * D_DIM]; // input lo
__device__ __align__(1024) __nv_bfloat16 g_Wh[2][512 * 256];  // weights [n][k] hi
__device__ __align__(1024) __nv_bfloat16 g_Wl[2][512 * 256];  // weights [n][k] lo
__device__ float g_biasC[2][512];
__device__ float g_Wf[2][256 * 256];          // W @ Wn per layer
__device__ float g_bf[2][256];                // b @ Wn + bn per layer
__device__ float g_dinv[NMAX];
__device__ int   g_cnt[NMAX];
__device__ int   g_rowstart[NMAX];
__device__ int   g_cursor[NMAX];
__device__ int   g_colidx[EMAX];
__device__ int   g_base;                      // global slot cursor

// ================= helpers =================================================
__device__ __forceinline__ uint32_t smem_u32(const void* p) {
    uint32_t a;
    asm("{ .reg .u64 t; cvta.to.shared.u64 t, %1; cvt.u32.u64 %0, t; }"
        : "=r"(a) : "l"(p));
    return a;
}
__device__ __forceinline__ void ldsm_x4(uint32_t* r, uint32_t addr) {
    asm volatile("ldmatrix.sync.aligned.m8n8.x4.shared.b16 {%0,%1,%2,%3}, [%4];"
                 : "=r"(r[0]), "=r"(r[1]), "=r"(r[2]), "=r"(r[3]) : "r"(addr));
}
__device__ __forceinline__ void mma_bf16(float* c, const uint32_t* a,
                                         uint32_t b0, uint32_t b1) {
    asm volatile(
        "mma.sync.aligned.m16n8k16.row.col.f32.bf16.bf16.f32 "
        "{%0,%1,%2,%3}, {%4,%5,%6,%7}, {%8,%9}, {%0,%1,%2,%3};"
        : "+f"(c[0]), "+f"(c[1]), "+f"(c[2]), "+f"(c[3])
        : "r"(a[0]), "r"(a[1]), "r"(a[2]), "r"(a[3]), "r"(b0), "r"(b1));
}
__device__ __forceinline__ void tma2d(uint32_t smem, const CUtensorMap* map,
                                      int x, int y, uint32_t mbar) {
    asm volatile(
        "cp.async.bulk.tensor.2d.shared::cta.global.tile.mbarrier::complete_tx::bytes "
        "[%0], [%1, {%2, %3}], [%4];"
        :: "r"(smem), "l"(map), "r"(x), "r"(y), "r"(mbar) : "memory");
}
#define MBAR_INIT(mb, c)  asm volatile("mbarrier.init.shared.b64 [%0], %1;" :: "r"(mb), "r"(c) : "memory")
#define MBAR_EXPECT_TX(mb, tx) asm volatile("mbarrier.arrive.expect_tx.shared.b64 _, [%0], %1;" :: "r"(mb), "r"(tx) : "memory")
#define MBAR_WAIT(mb, par) do {                                              \
    uint32_t _mb = (mb), _p = (par), _done;                                  \
    asm volatile("{\n\t.reg .pred p;\n\t"                                    \
        "mbarrier.try_wait.parity.acquire.cta.shared::cta.b64 p, [%1], %2;\n\t" \
        "selp.b32 %0, 1, 0, p;\n\t}" : "=r"(_done) : "r"(_mb), "r"(_p) : "memory"); \
    if (!_done) {                                                            \
        asm volatile("{\n\t.reg .pred P1;\n\t"                               \
            "WL_%=:\n\t"                                                     \
            "mbarrier.try_wait.parity.acquire.cta.shared::cta.b64 P1, [%0], %1, 0x989680;\n\t" \
            "@P1 bra.uni WD_%=;\n\tbra.uni WL_%=;\n\tWD_%=:\n\t}"            \
            :: "r"(_mb), "r"(_p) : "memory");                                \
    }                                                                        \
} while (0)
#define SW128(off) ((off) ^ (((off) >> 3) & 0x70))

// ---------------- CSR build (scan-free) ------------------------------------
__global__ void count_edges_kernel(const int* __restrict__ row, int e) {
    int i = blockIdx.x * blockDim.x + threadIdx.x;
    if (i < e) atomicAdd(&g_cnt[row[i]], 1);
}
__global__ void offsets_kernel(int n) {
    int i = blockIdx.x * blockDim.x + threadIdx.x;
    int lane = threadIdx.x & 31;
    int c = (i < n) ? g_cnt[i] : 0;
    int incl = c;
    #pragma unroll
    for (int o = 1; o < 32; o <<= 1) {
        int v = __shfl_up_sync(0xffffffffu, incl, o);
        if (lane >= o) incl += v;
    }
    int total = __shfl_sync(0xffffffffu, incl, 31);
    int base = 0;
    if (lane == 31 && total > 0) base = atomicAdd(&g_base, total);
    base = __shfl_sync(0xffffffffu, base, 31);
    if (i < n) {
        int start = base + incl - c;
        g_rowstart[i] = start;
        g_cursor[i]   = start;
        g_dinv[i]     = rsqrtf((float)(c + 1));
    }
}
__global__ void fill_csr_kernel(const int* __restrict__ row,
                                const int* __restrict__ col, int e) {
    int i = blockIdx.x * blockDim.x + threadIdx.x;
    if (i < e) {
        int p = atomicAdd(&g_cursor[row[i]], 1);
        g_colidx[p] = col[i];
    }
}

// ---------------- weight prep ---------------------------------------------
// smem-tiled Wf = W @ Wn (both layers): grid (8,8,2), block (32,8)
__global__ void fuse_wf_kernel(const float* __restrict__ W0,
                               const float* __restrict__ Wn0,
                               const float* __restrict__ W1,
                               const float* __restrict__ Wn1) {
    __shared__ float sW[32][33], sWn[32][33];
    int layer = blockIdx.z;
    const float* W  = layer ? W1  : W0;
    const float* Wn = layer ? Wn1 : Wn0;
    int k0 = blockIdx.x * 32, n0 = blockIdx.y * 32;
    int tx = threadIdx.x, ty = threadIdx.y;
    float acc[4] = {0.f, 0.f, 0.f, 0.f};
    for (int j0 = 0; j0 < 256; j0 += 32) {
        #pragma unroll
        for (int i = 0; i < 4; i++) {
            sW[ty + 8 * i][tx]  = W[(k0 + ty + 8 * i) * 256 + j0 + tx];
            sWn[ty + 8 * i][tx] = Wn[(j0 + ty + 8 * i) * 256 + n0 + tx];
        }
        __syncthreads();
        #pragma unroll
        for (int j = 0; j < 32; j++) {
            float wn = sWn[j][tx];
            #pragma unroll
            for (int i = 0; i < 4; i++)
                acc[i] = fmaf(sW[ty + 8 * i][j], wn, acc[i]);
        }
        __syncthreads();
    }
    #pragma unroll
    for (int i = 0; i < 4; i++)
        g_Wf[layer][(k0 + ty + 8 * i) * 256 + n0 + tx] = acc[i];
}
// bf = b @ Wn + bn (both layers): grid 2, block 256
__global__ void fuse_b_kernel(const float* __restrict__ b0,
                              const float* __restrict__ Wn0,
                              const float* __restrict__ bn0,
                              const float* __restrict__ b1,
                              const float* __restrict__ Wn1,
                              const float* __restrict__ bn1) {
    int layer = blockIdx.x;
    const float* b  = layer ? b1  : b0;
    const float* Wn = layer ? Wn1 : Wn0;
    const float* bn = layer ? bn1 : bn0;
    int n = threadIdx.x;
    float acc = bn[n];
    #pragma unroll 8
    for (int j = 0; j < 256; j++)
        acc = fmaf(__ldg(b + j), Wn[(size_t)j * 256 + n], acc);
    g_bf[layer][n] = acc;
}
__global__ void pack_w_kernel(const float* __restrict__ W0,
                              const float* __restrict__ b0,
                              const float* __restrict__ W1,
                              const float* __restrict__ b1) {
    __shared__ float s[32][33];
    int layer = blockIdx.z;
    const float* W = layer ? W1 : W0;
    const float* b = layer ? b1 : b0;
    int k0 = blockIdx.x * 32, n0 = blockIdx.y * 32;
    int tx = threadIdx.x, ty = threadIdx.y;
    #pragma unroll
    for (int i = 0; i < 4; i++) {
        int k = k0 + ty + i * 8;
        float v = (n0 < 256) ? W[k * 256 + n0 + tx]
                             : g_Wf[layer][k * 256 + (n0 - 256) + tx];
        s[ty + i * 8][tx] = v;
    }
    __syncthreads();
    #pragma unroll
    for (int i = 0; i < 4; i++) {
        int n = n0 + ty + i * 8;
        float w = s[tx][ty + i * 8];
        __nv_bfloat16 hi = __float2bfloat16(w);
        g_Wh[layer][n * 256 + k0 + tx] = hi;
        g_Wl[layer][n * 256 + k0 + tx] = __float2bfloat16(w - __bfloat162float(hi));
    }
    if (blockIdx.x == 0 && tx == 0) {
        #pragma unroll
        for (int i = 0; i < 4; i++) {
            int n = n0 + ty + i * 8;
            g_biasC[layer][n] = (n < 256) ? b[n] : g_bf[layer][n - 256];
        }
    }
}
__global__ void split_kernel(const float* __restrict__ x, int total4) {
    int i = blockIdx.x * blockDim.x + threadIdx.x;
    if (i < total4) {
        float4 v = reinterpret_cast<const float4*>(x)[i];
        __nv_bfloat16 h0 = __float2bfloat16(v.x), h1 = __float2bfloat16(v.y);
        __nv_bfloat16 h2 = __float2bfloat16(v.z), h3 = __float2bfloat16(v.w);
        __nv_bfloat162 hA, hB, lA, lB;
        hA.x = h0; hA.y = h1; hB.x = h2; hB.y = h3;
        lA.x = __float2bfloat16(v.x - __bfloat162float(h0));
        lA.y = __float2bfloat16(v.y - __bfloat162float(h1));
        lB.x = __float2bfloat16(v.z - __bfloat162float(h2));
        lB.y = __float2bfloat16(v.w - __bfloat162float(h3));
        reinterpret_cast<__nv_bfloat162*>(g_Ah)[i * 2]     = hA;
        reinterpret_cast<__nv_bfloat162*>(g_Ah)[i * 2 + 1] = hB;
        reinterpret_cast<__nv_bfloat162*>(g_Al)[i * 2]     = lA;
        reinterpret_cast<__nv_bfloat162*>(g_Al)[i * 2 + 1] = lB;
    }
}

// ---------------- HMMA GEMM: [B|C] = A @ Wcomb, split-bf16 x3, TMA loads ---
// 512 threads, 16 warps in 4x4 grid, warp tile 32x32.
#define STAGE_BYTES 65536
__global__ __launch_bounds__(512)
void hmma_gemm_kernel(const __grid_constant__ CUtensorMap tmAh,
                      const __grid_constant__ CUtensorMap tmAl,
                      const __grid_constant__ CUtensorMap tmWh,
                      const __grid_constant__ CUtensorMap tmWl,
                      int wyoff,
                      const float* __restrict__ bias,
                      float* __restrict__ Bout, float* __restrict__ Cout,
                      __half* __restrict__ Yh, const float* __restrict__ dinv,
                      int M)
{
    extern __shared__ char dsm_raw[];
    __shared__ __align__(8) unsigned long long s_mbar[2];
    uint32_t dynu = smem_u32(dsm_raw);
    uint32_t pad = ((dynu + 1023) & ~1023u) - dynu;
    uint32_t sb = dynu + pad;
    const uint32_t OFF_AH = 0, OFF_AL = 16384, OFF_BH = 32768, OFF_BL = 49152;

    int tid  = threadIdx.x;
    int warp = tid >> 5, lane = tid & 31;
    int brow = blockIdx.x * 128;
    int ncb  = blockIdx.y * 128;
    int wm   = (warp >> 2) * 32;
    int wn   = (warp & 3) * 32;

    uint32_t mb0 = smem_u32(&s_mbar[0]);
    uint32_t mb1 = smem_u32(&s_mbar[1]);
    if (tid == 0) { MBAR_INIT(mb0, 1); MBAR_INIT(mb1, 1); }
    __syncthreads();

    float acc[2][4][4];
    #pragma unroll
    for (int mi = 0; mi < 2; mi++)
        #pragma unroll
        for (int ni = 0; ni < 4; ni++)
            #pragma unroll
            for (int q = 0; q < 4; q++) acc[mi][ni][q] = 0.0f;

    auto load_chunk = [&](int chunk, int stage) {
        int k0 = chunk * 64;
        uint32_t sbase = sb + stage * STAGE_BYTES;
        uint32_t mb = stage ? mb1 : mb0;
        MBAR_EXPECT_TX(mb, (uint32_t)STAGE_BYTES);
        tma2d(sbase + OFF_AH, &tmAh, k0, brow, mb);
        tma2d(sbase + OFF_AL, &tmAl, k0, brow, mb);
        tma2d(sbase + OFF_BH, &tmWh, k0, wyoff + ncb, mb);
        tma2d(sbase + OFF_BL, &tmWl, k0, wyoff + ncb, mb);
    };

    if (tid == 0) load_chunk(0, 0);

    for (int chunk = 0; chunk < 4; chunk++) {
        int stage = chunk & 1;
        if (chunk < 3 && tid == 0) load_chunk(chunk + 1, stage ^ 1);
        MBAR_WAIT(stage ? mb1 : mb0, (chunk >> 1) & 1);

        uint32_t sbase = sb + stage * STAGE_BYTES;
        #pragma unroll
        for (int ks = 0; ks < 4; ks++) {
            uint32_t kb   = (uint32_t)(ks * 32 + ((lane >> 4) & 1) * 16);
            uint32_t kswz = kb ^ ((uint32_t)(lane & 7) << 4);
            uint32_t rsub = (uint32_t)((lane & 7) + ((lane >> 3) & 1) * 8);

            uint32_t adA = sbase + (wm + rsub) * 128 + kswz;
            uint32_t adB = sbase + (wn + rsub) * 128 + kswz;

            uint32_t a[2][4];                    // reused: hi then lo
            uint32_t bh[2][4], bl[2][4];
            #pragma unroll
            for (int mi = 0; mi < 2; mi++)
                ldsm_x4(a[mi], adA + OFF_AH + mi * 2048);
            #pragma unroll
            for (int nj = 0; nj < 2; nj++) {
                ldsm_x4(bh[nj], adB + OFF_BH + nj * 2048);
                ldsm_x4(bl[nj], adB + OFF_BL + nj * 2048);
            }
            #pragma unroll
            for (int mi = 0; mi < 2; mi++)
                #pragma unroll
                for (int ni = 0; ni < 4; ni++) {
                    int nj = ni >> 1, sel = ni & 1;
                    mma_bf16(acc[mi][ni], a[mi], bh[nj][sel], bh[nj][sel + 2]);
                    mma_bf16(acc[mi][ni], a[mi], bl[nj][sel], bl[nj][sel + 2]);
                }
            #pragma unroll
            for (int mi = 0; mi < 2; mi++)
                ldsm_x4(a[mi], adA + OFF_AL + mi * 2048);
            #pragma unroll
            for (int mi = 0; mi < 2; mi++)
                #pragma unroll
                for (int ni = 0; ni < 4; ni++) {
                    int nj = ni >> 1, sel = ni & 1;
                    mma_bf16(acc[mi][ni], a[mi], bh[nj][sel], bh[nj][sel + 2]);
                }
        }
        __syncthreads();
    }

    bool chalf = (ncb >= 256);
    int  cbase = chalf ? (ncb - 256) : ncb;
    #pragma unroll
    for (int mi = 0; mi < 2; mi++) {
        int row0 = brow + wm + mi * 16 + (lane >> 2);
        int row1 = row0 + 8;
        #pragma unroll
        for (int ni = 0; ni < 4; ni++) {
            int gcol = cbase + wn + ni * 8 + (lane & 3) * 2;
            float2 bb = *(const float2*)(bias + (chalf ? 256 : 0) + gcol);
            float2 v0, v1;
            v0.x = acc[mi][ni][0] + bb.x; v0.y = acc[mi][ni][1] + bb.y;
            v1.x = acc[mi][ni][2] + bb.x; v1.y = acc[mi][ni][3] + bb.y;
            if (!chalf) {
                if (row0 < M) *(float2*)(Bout + (size_t)row0 * 256 + gcol) = v0;
                if (row1 < M) *(float2*)(Bout + (size_t)row1 * 256 + gcol) = v1;
            } else {
                if (row0 < M) {
                    float di = dinv[row0];
                    *(float2*)(Cout + (size_t)row0 * 256 + gcol) = v0;
                    *(__half2*)(Yh + (size_t)row0 * 256 + gcol) =
                        __floats2half2_rn(di * v0.x, di * v0.y);
                }
                if (row1 < M) {
                    float di = dinv[row1];
                    *(float2*)(Cout + (size_t)row1 * 256 + gcol) = v1;
                    *(__half2*)(Yh + (size_t)row1 * 256 + gcol) =
                        __floats2half2_rn(di * v1.x, di * v1.y);
                }
            }
        }
    }
}

// ---------------- fused aggregate + mix + l2norm + relu -> bf16 hi/lo ------
__global__ __launch_bounds__(256)
void agg_combine_kernel(const float* __restrict__ Bm, const float* __restrict__ C,
                        const __half* __restrict__ Yh, int M)
{
    int i = blockIdx.x;
    int t = threadIdx.x;
    if (i >= M) return;

    int g = t >> 5;          // warp 0..7 = neighbor group
    int sl = t & 31;         // lane = feature chunk (8 halves)

    __shared__ int cols[256];
    __shared__ float sacc[8][256];
    __shared__ float wsum[8];

    int s = g_rowstart[i];
    int e = s + g_cnt[i];

    float facc[8];
    #pragma unroll
    for (int q = 0; q < 8; q++) facc[q] = 0.0f;

    for (int base = s; base < e; base += 256) {
        int m = min(256, e - base);
        if (t < m) cols[t] = g_colidx[base + t];
        __syncthreads();
        for (int j = g; j < m; j += 8) {
            const __half* yrow = Yh + (size_t)cols[j] * D_DIM + sl * 8;
            uint4 v = *reinterpret_cast<const uint4*>(yrow);
            const __half2* hp = reinterpret_cast<const __half2*>(&v);
            #pragma unroll
            for (int q = 0; q < 4; q++) {
                float2 f = __half22float2(hp[q]);
                facc[q * 2]     += f.x;
                facc[q * 2 + 1] += f.y;
            }
        }
        __syncthreads();
    }
    #pragma unroll
    for (int q = 0; q < 8; q++) sacc[g][sl * 8 + q] = facc[q];
    __syncthreads();

    float acc = 0.0f;
    #pragma unroll
    for (int g2 = 0; g2 < 8; g2++) acc += sacc[g2][t];

    float di = g_dinv[i];
    float nb = C[(size_t)i * D_DIM + t];
    float prop = di * acc + di * di * nb;
    float h = Bm[(size_t)i * D_DIM + t] + 0.5f * prop + 0.5f * nb;

    float v = h * h;
    #pragma unroll
    for (int o = 16; o > 0; o >>= 1)
        v += __shfl_xor_sync(0xffffffffu, v, o);
    if ((t & 31) == 0) wsum[t >> 5] = v;
    __syncthreads();
    float tot = 0.0f;
    #pragma unroll
    for (int w = 0; w < 8; w++) tot += wsum[w];
    float nrm = sqrtf(tot);
    h = fmaxf(h / fmaxf(nrm, 1e-12f), 0.0f);

    __nv_bfloat16 hi = __float2bfloat16(h);
    size_t off = (size_t)i * D_DIM + t;
    g_Ah[off] = hi;
    g_Al[off] = __float2bfloat16(h - __bfloat162float(hi));
}

// ---------------- output GEMM: Out[M,32] = (Hh+Hl) @ W2 + b2 ---------------
// 64 rows/block: halves the W2 re-read traffic vs 32 rows/block.
__global__ __launch_bounds__(256)
void gemm_out_kernel(const float* __restrict__ W2,
                     const float* __restrict__ b2, float* __restrict__ Out, int M)
{
    extern __shared__ __align__(16) float smem[];
    float* sW = smem;                 // [256][32] (32KB)
    float* sH = smem + D_DIM * 32;    // [64][256] (64KB)

    int tid  = threadIdx.x;
    int brow = blockIdx.x * 64;

    #pragma unroll
    for (int l = 0; l < 8; l++) {
        int idx = tid + l * 256;
        reinterpret_cast<float4*>(sW)[idx] = reinterpret_cast<const float4*>(W2)[idx];
    }
    #pragma unroll
    for (int l = 0; l < 32; l++) {
        int idx = tid + l * 256;       // bf16x2 index into 64x256 (8192 total)
        int r = idx >> 7, c2 = idx & 127;
        float2 f = make_float2(0.f, 0.f);
        if (brow + r < M) {
            size_t off = (size_t)(brow + r) * D_DIM + c2 * 2;
            __nv_bfloat162 hv = *(const __nv_bfloat162*)(g_Ah + off);
            __nv_bfloat162 lv = *(const __nv_bfloat162*)(g_Al + off);
            f.x = __bfloat162float(hv.x) + __bfloat162float(lv.x);
            f.y = __bfloat162float(hv.y) + __bfloat162float(lv.y);
        }
        *reinterpret_cast<float2*>(sH + r * D_DIM + c2 * 2) = f;
    }
    __syncthreads();

    int ry = tid >> 3;            // 0..31; handles rows ry and ry+32
    int c4 = (tid & 7) * 4;
    float4 acc0 = make_float4(0.f, 0.f, 0.f, 0.f);
    float4 acc1 = make_float4(0.f, 0.f, 0.f, 0.f);
    #pragma unroll 8
    for (int k = 0; k < D_DIM; k++) {
        float4 w = *reinterpret_cast<const float4*>(&sW[k * 32 + c4]);
        float h0 = sH[ry * D_DIM + k];
        float h1 = sH[(ry + 32) * D_DIM + k];
        acc0.x = fmaf(h0, w.x, acc0.x); acc0.y = fmaf(h0, w.y, acc0.y);
        acc0.z = fmaf(h0, w.z, acc0.z); acc0.w = fmaf(h0, w.w, acc0.w);
        acc1.x = fmaf(h1, w.x, acc1.x); acc1.y = fmaf(h1, w.y, acc1.y);
        acc1.z = fmaf(h1, w.z, acc1.z); acc1.w = fmaf(h1, w.w, acc1.w);
    }
    float4 bb = *reinterpret_cast<const float4*>(b2 + c4);
    int grow0 = brow + ry, grow1 = brow + ry + 32;
    if (grow0 < M) {
        float4 o; o.x = acc0.x + bb.x; o.y = acc0.y + bb.y;
        o.z = acc0.z + bb.z; o.w = acc0.w + bb.w;
        *reinterpret_cast<float4*>(Out + (size_t)grow0 * O_DIM + c4) = o;
    }
    if (grow1 < M) {
        float4 o; o.x = acc1.x + bb.x; o.y = acc1.y + bb.y;
        o.z = acc1.z + bb.z; o.w = acc1.w + bb.w;
        *reinterpret_cast<float4*>(Out + (size_t)grow1 * O_DIM + c4) = o;
    }
}

// ---------------- host launcher (single stream) ----------------------------
typedef CUresult (CUDAAPI *PFN_encTiled)(
    CUtensorMap*, CUtensorMapDataType, cuuint32_t, void*,
    const cuuint64_t*, const cuuint64_t*, const cuuint32_t*, const cuuint32_t*,
    CUtensorMapInterleave, CUtensorMapSwizzle, CUtensorMapL2promotion,
    CUtensorMapFloatOOBfill);

extern "C" void kernel_launch(void* const* d_in, const int* in_sizes, int n_in,
                              void* d_out, int out_size)
{
    const float* x   = (const float*)d_in[0];
    const int*   ei  = (const int*)  d_in[1];
    const float* W0  = (const float*)d_in[2];
    const float* b0  = (const float*)d_in[3];
    const float* Wn0 = (const float*)d_in[4];
    const float* bn0 = (const float*)d_in[5];
    const float* W1  = (const float*)d_in[6];
    const float* b1  = (const float*)d_in[7];
    const float* Wn1 = (const float*)d_in[8];
    const float* bn1 = (const float*)d_in[9];
    const float* W2  = (const float*)d_in[10];
    const float* b2  = (const float*)d_in[11];

    int M = in_sizes[0] / D_DIM;
    int E = in_sizes[1] / 2;
    const int* erow = ei;
    const int* ecol = ei + E;

    float *pB, *pC, *pBiasC, *pDinv;
    __half* pYh;
    __nv_bfloat16 *pAh, *pAl, *pWh, *pWl;
    int *pCnt, *pBase;
    cudaGetSymbolAddress((void**)&pB,    g_B);
    cudaGetSymbolAddress((void**)&pC,    g_C);
    cudaGetSymbolAddress((void**)&pYh,   g_Yh);
    cudaGetSymbolAddress((void**)&pDinv, g_dinv);
    cudaGetSymbolAddress((void**)&pAh,   g_Ah);
    cudaGetSymbolAddress((void**)&pAl,   g_Al);
    cudaGetSymbolAddress((void**)&pWh,   g_Wh);
    cudaGetSymbolAddress((void**)&pWl,   g_Wl);
    cudaGetSymbolAddress((void**)&pBiasC, g_biasC);
    cudaGetSymbolAddress((void**)&pCnt,  g_cnt);
    cudaGetSymbolAddress((void**)&pBase, g_base);

    static CUtensorMap tmAh, tmAl, tmWh, tmWl;
    static bool init_done = false;
    if (!init_done) {
        cudaFuncSetAttribute(hmma_gemm_kernel,
                             cudaFuncAttributeMaxDynamicSharedMemorySize,
                             2 * STAGE_BYTES + 1024);
        cudaFuncSetAttribute(gemm_out_kernel,
                             cudaFuncAttributeMaxDynamicSharedMemorySize, 98304);

        void* fp = nullptr;
        cudaDriverEntryPointQueryResult qr;
#if CUDART_VERSION >= 12050
        cudaGetDriverEntryPointByVersion("cuTensorMapEncodeTiled", &fp, 12000,
                                         cudaEnableDefault, &qr);
#else
        cudaGetDriverEntryPoint("cuTensorMapEncodeTiled", &fp,
                                cudaEnableDefault, &qr);
#endif
        PFN_encTiled enc = (PFN_encTiled)fp;

        cuuint64_t dimsA[2] = {256, (cuuint64_t)M};
        cuuint64_t strA[1]  = {256 * 2};
        cuuint64_t dimsW[2] = {256, 1024};
        cuuint64_t strW[1]  = {256 * 2};
        cuuint32_t box[2]   = {64, 128};
        cuuint32_t estr[2]  = {1, 1};
        enc(&tmAh, CU_TENSOR_MAP_DATA_TYPE_BFLOAT16, 2, pAh, dimsA, strA, box,
            estr, CU_TENSOR_MAP_INTERLEAVE_NONE, CU_TENSOR_MAP_SWIZZLE_128B,
            CU_TENSOR_MAP_L2_PROMOTION_L2_128B, CU_TENSOR_MAP_FLOAT_OOB_FILL_NONE);
        enc(&tmAl, CU_TENSOR_MAP_DATA_TYPE_BFLOAT16, 2, pAl, dimsA, strA, box,
            estr, CU_TENSOR_MAP_INTERLEAVE_NONE, CU_TENSOR_MAP_SWIZZLE_128B,
            CU_TENSOR_MAP_L2_PROMOTION_L2_128B, CU_TENSOR_MAP_FLOAT_OOB_FILL_NONE);
        enc(&tmWh, CU_TENSOR_MAP_DATA_TYPE_BFLOAT16, 2, pWh, dimsW, strW, box,
            estr, CU_TENSOR_MAP_INTERLEAVE_NONE, CU_TENSOR_MAP_SWIZZLE_128B,
            CU_TENSOR_MAP_L2_PROMOTION_L2_128B, CU_TENSOR_MAP_FLOAT_OOB_FILL_NONE);
        enc(&tmWl, CU_TENSOR_MAP_DATA_TYPE_BFLOAT16, 2, pWl, dimsW, strW, box,
            estr, CU_TENSOR_MAP_INTERLEAVE_NONE, CU_TENSOR_MAP_SWIZZLE_128B,
            CU_TENSOR_MAP_L2_PROMOTION_L2_128B, CU_TENSOR_MAP_FLOAT_OOB_FILL_NONE);
        init_done = true;
    }

    int eb = (E + 255) / 256;
    int nb = (M + 255) / 256;
    dim3 gg((M + 127) / 128, 4);
    dim3 wfgrid(8, 8, 2), wfblk(32, 8);
    dim3 pgrid(8, 16, 2), pblk(32, 8);

    // CSR build + dinv (before GEMM: its epilogue reads dinv)
    cudaMemsetAsync(pCnt, 0, (size_t)M * sizeof(int));
    cudaMemsetAsync(pBase, 0, sizeof(int));
    count_edges_kernel<<<eb, 256>>>(erow, E);
    offsets_kernel<<<nb, 256>>>(M);
    fill_csr_kernel<<<eb, 256>>>(erow, ecol, E);

    // weight prep (both layers)
    fuse_wf_kernel<<<wfgrid, wfblk>>>(W0, Wn0, W1, Wn1);
    fuse_b_kernel<<<2, 256>>>(b0, Wn0, bn0, b1, Wn1, bn1);
    pack_w_kernel<<<pgrid, pblk>>>(W0, b0, W1, b1);

    // split input
    split_kernel<<<(M * D_DIM / 4 + 255) / 256, 256>>>(x, M * D_DIM / 4);

    // layer 1
    hmma_gemm_kernel<<<gg, 512, 2 * STAGE_BYTES + 1024>>>(
        tmAh, tmAl, tmWh, tmWl, 0, pBiasC, pB, pC, pYh, pDinv, M);
    agg_combine_kernel<<<M, 256>>>(pB, pC, pYh, M);

    // layer 2
    hmma_gemm_kernel<<<gg, 512, 2 * STAGE_BYTES + 1024>>>(
        tmAh, tmAl, tmWh, tmWl, 512, pBiasC + 512, pB, pC, pYh, pDinv, M);
    agg_combine_kernel<<<M, 256>>>(pB, pC, pYh, M);

    // output layer
    gemm_out_kernel<<<(M + 63) / 64, 256, 98304>>>(W2, b2, (float*)d_out, M);
}

// round 16
// speedup vs baseline: 1.5792x; 1.0300x over previous
#include <cuda_runtime.h>
#include <cuda.h>
#include <cuda_bf16.h>
#include <cuda_fp16.h>
#include <math.h>
#include <stdint.h>

#define D_DIM 256
#define O_DIM 32
#define NMAX 50000
#define EMAX 800000

// ---------------- scratch (static device globals; no runtime allocation) ---
__device__ float g_B[(size_t)NMAX * D_DIM];   // h1 = A@W+b
__device__ __align__(1024) __half g_Ch[(size_t)NMAX * D_DIM]; // nb fp16
__device__ __align__(1024) __half g_Yh[(size_t)NMAX * D_DIM]; // dinv*nb fp16
__device__ __align__(1024) __nv_bfloat16 g_Ah[(size_t)NMAX * D_DIM]; // input hi
__device__ __align__(1024) __nv_bfloat16 g_Al[(size_t)NMAX * D_DIM]; // input lo
__device__ __align__(1024) __nv_bfloat16 g_Wh[2][512 * 256];  // weights [n][k] hi
__device__ __align__(1024) __nv_bfloat16 g_Wl[2][512 * 256];  // weights [n][k] lo
__device__ float g_biasC[2][512];
__device__ float g_WfP[2][2][256 * 256];      // partial W@Wn (layer, k-half)
__device__ float g_bf[2][256];                // b @ Wn + bn per layer
__device__ float g_dinv[NMAX];
__device__ int   g_cnt[NMAX];
__device__ int   g_rowstart[NMAX];
__device__ int   g_cursor[NMAX];
__device__ int   g_colidx[EMAX];
__device__ int   g_base;                      // global slot cursor

// ================= helpers =================================================
__device__ __forceinline__ uint32_t smem_u32(const void* p) {
    uint32_t a;
    asm("{ .reg .u64 t; cvta.to.shared.u64 t, %1; cvt.u32.u64 %0, t; }"
        : "=r"(a) : "l"(p));
    return a;
}
__device__ __forceinline__ void ldsm_x4(uint32_t* r, uint32_t addr) {
    asm volatile("ldmatrix.sync.aligned.m8n8.x4.shared.b16 {%0,%1,%2,%3}, [%4];"
                 : "=r"(r[0]), "=r"(r[1]), "=r"(r[2]), "=r"(r[3]) : "r"(addr));
}
__device__ __forceinline__ void mma_bf16(float* c, const uint32_t* a,
                                         uint32_t b0, uint32_t b1) {
    asm volatile(
        "mma.sync.aligned.m16n8k16.row.col.f32.bf16.bf16.f32 "
        "{%0,%1,%2,%3}, {%4,%5,%6,%7}, {%8,%9}, {%0,%1,%2,%3};"
        : "+f"(c[0]), "+f"(c[1]), "+f"(c[2]), "+f"(c[3])
        : "r"(a[0]), "r"(a[1]), "r"(a[2]), "r"(a[3]), "r"(b0), "r"(b1));
}
__device__ __forceinline__ void tma2d(uint32_t smem, const CUtensorMap* map,
                                      int x, int y, uint32_t mbar) {
    asm volatile(
        "cp.async.bulk.tensor.2d.shared::cta.global.tile.mbarrier::complete_tx::bytes "
        "[%0], [%1, {%2, %3}], [%4];"
        :: "r"(smem), "l"(map), "r"(x), "r"(y), "r"(mbar) : "memory");
}
#define MBAR_INIT(mb, c)  asm volatile("mbarrier.init.shared.b64 [%0], %1;" :: "r"(mb), "r"(c) : "memory")
#define MBAR_EXPECT_TX(mb, tx) asm volatile("mbarrier.arrive.expect_tx.shared.b64 _, [%0], %1;" :: "r"(mb), "r"(tx) : "memory")
#define MBAR_WAIT(mb, par) do {                                              \
    uint32_t _mb = (mb), _p = (par), _done;                                  \
    asm volatile("{\n\t.reg .pred p;\n\t"                                    \
        "mbarrier.try_wait.parity.acquire.cta.shared::cta.b64 p, [%1], %2;\n\t" \
        "selp.b32 %0, 1, 0, p;\n\t}" : "=r"(_done) : "r"(_mb), "r"(_p) : "memory"); \
    if (!_done) {                                                            \
        asm volatile("{\n\t.reg .pred P1;\n\t"                               \
            "WL_%=:\n\t"                                                     \
            "mbarrier.try_wait.parity.acquire.cta.shared::cta.b64 P1, [%0], %1, 0x989680;\n\t" \
            "@P1 bra.uni WD_%=;\n\tbra.uni WL_%=;\n\tWD_%=:\n\t}"            \
            :: "r"(_mb), "r"(_p) : "memory");                                \
    }                                                                        \
} while (0)
#define SW128(off) ((off) ^ (((off) >> 3) & 0x70))

// ---------------- CSR build (scan-free) ------------------------------------
__global__ void count_edges_kernel(const int* __restrict__ row, int e) {
    int i = blockIdx.x * blockDim.x + threadIdx.x;
    if (i < e) atomicAdd(&g_cnt[row[i]], 1);
}
__global__ void offsets_kernel(int n) {
    int i = blockIdx.x * blockDim.x + threadIdx.x;
    int lane = threadIdx.x & 31;
    int c = (i < n) ? g_cnt[i] : 0;
    int incl = c;
    #pragma unroll
    for (int o = 1; o < 32; o <<= 1) {
        int v = __shfl_up_sync(0xffffffffu, incl, o);
        if (lane >= o) incl += v;
    }
    int total = __shfl_sync(0xffffffffu, incl, 31);
    int base = 0;
    if (lane == 31 && total > 0) base = atomicAdd(&g_base, total);
    base = __shfl_sync(0xffffffffu, base, 31);
    if (i < n) {
        int start = base + incl - c;
        g_rowstart[i] = start;
        g_cursor[i]   = start;
        g_dinv[i]     = rsqrtf((float)(c + 1));
    }
}
__global__ void fill_csr_kernel(const int* __restrict__ row,
                                const int* __restrict__ col, int e) {
    int i = blockIdx.x * blockDim.x + threadIdx.x;
    if (i < e) {
        int p = atomicAdd(&g_cursor[row[i]], 1);
        g_colidx[p] = col[i];
    }
}

// ---------------- weight prep ---------------------------------------------
// smem-tiled partial Wf = W @ Wn, k-split x2: grid (8,8,4) z=layer*2+part
__global__ void fuse_wf_kernel(const float* __restrict__ W0,
                               const float* __restrict__ Wn0,
                               const float* __restrict__ W1,
                               const float* __restrict__ Wn1) {
    __shared__ float sW[32][33], sWn[32][33];
    int layer = blockIdx.z >> 1, part = blockIdx.z & 1;
    const float* W  = layer ? W1  : W0;
    const float* Wn = layer ? Wn1 : Wn0;
    int k0 = blockIdx.x * 32, n0 = blockIdx.y * 32;
    int tx = threadIdx.x, ty = threadIdx.y;
    float acc[4] = {0.f, 0.f, 0.f, 0.f};
    int jbeg = part * 128, jend = jbeg + 128;
    for (int j0 = jbeg; j0 < jend; j0 += 32) {
        #pragma unroll
        for (int i = 0; i < 4; i++) {
            sW[ty + 8 * i][tx]  = W[(k0 + ty + 8 * i) * 256 + j0 + tx];
            sWn[ty + 8 * i][tx] = Wn[(j0 + ty + 8 * i) * 256 + n0 + tx];
        }
        __syncthreads();
        #pragma unroll
        for (int j = 0; j < 32; j++) {
            float wn = sWn[j][tx];
            #pragma unroll
            for (int i = 0; i < 4; i++)
                acc[i] = fmaf(sW[ty + 8 * i][j], wn, acc[i]);
        }
        __syncthreads();
    }
    #pragma unroll
    for (int i = 0; i < 4; i++)
        g_WfP[layer][part][(k0 + ty + 8 * i) * 256 + n0 + tx] = acc[i];
}
// bf = b @ Wn + bn (both layers)
__global__ void fuse_b_kernel(const float* __restrict__ b0,
                              const float* __restrict__ Wn0,
                              const float* __restrict__ bn0,
                              const float* __restrict__ b1,
                              const float* __restrict__ Wn1,
                              const float* __restrict__ bn1) {
    int layer = blockIdx.x;
    const float* b  = layer ? b1  : b0;
    const float* Wn = layer ? Wn1 : Wn0;
    const float* bn = layer ? bn1 : bn0;
    int n = threadIdx.x;
    float acc = bn[n];
    #pragma unroll 8
    for (int j = 0; j < 256; j++)
        acc = fmaf(__ldg(b + j), Wn[(size_t)j * 256 + n], acc);
    g_bf[layer][n] = acc;
}
__global__ void pack_w_kernel(const float* __restrict__ W0,
                              const float* __restrict__ b0,
                              const float* __restrict__ W1,
                              const float* __restrict__ b1) {
    __shared__ float s[32][33];
    int layer = blockIdx.z;
    const float* W = layer ? W1 : W0;
    const float* b = layer ? b1 : b0;
    int k0 = blockIdx.x * 32, n0 = blockIdx.y * 32;
    int tx = threadIdx.x, ty = threadIdx.y;
    #pragma unroll
    for (int i = 0; i < 4; i++) {
        int k = k0 + ty + i * 8;
        float v;
        if (n0 < 256) v = W[k * 256 + n0 + tx];
        else {
            int idx = k * 256 + (n0 - 256) + tx;
            v = g_WfP[layer][0][idx] + g_WfP[layer][1][idx];
        }
        s[ty + i * 8][tx] = v;
    }
    __syncthreads();
    #pragma unroll
    for (int i = 0; i < 4; i++) {
        int n = n0 + ty + i * 8;
        float w = s[tx][ty + i * 8];
        __nv_bfloat16 hi = __float2bfloat16(w);
        g_Wh[layer][n * 256 + k0 + tx] = hi;
        g_Wl[layer][n * 256 + k0 + tx] = __float2bfloat16(w - __bfloat162float(hi));
    }
    if (blockIdx.x == 0 && tx == 0) {
        #pragma unroll
        for (int i = 0; i < 4; i++) {
            int n = n0 + ty + i * 8;
            g_biasC[layer][n] = (n < 256) ? b[n] : g_bf[layer][n - 256];
        }
    }
}
__global__ void split_kernel(const float* __restrict__ x, int total4) {
    int i = blockIdx.x * blockDim.x + threadIdx.x;
    if (i < total4) {
        float4 v = reinterpret_cast<const float4*>(x)[i];
        __nv_bfloat16 h0 = __float2bfloat16(v.x), h1 = __float2bfloat16(v.y);
        __nv_bfloat16 h2 = __float2bfloat16(v.z), h3 = __float2bfloat16(v.w);
        __nv_bfloat162 hA, hB, lA, lB;
        hA.x = h0; hA.y = h1; hB.x = h2; hB.y = h3;
        lA.x = __float2bfloat16(v.x - __bfloat162float(h0));
        lA.y = __float2bfloat16(v.y - __bfloat162float(h1));
        lB.x = __float2bfloat16(v.z - __bfloat162float(h2));
        lB.y = __float2bfloat16(v.w - __bfloat162float(h3));
        reinterpret_cast<__nv_bfloat162*>(g_Ah)[i * 2]     = hA;
        reinterpret_cast<__nv_bfloat162*>(g_Ah)[i * 2 + 1] = hB;
        reinterpret_cast<__nv_bfloat162*>(g_Al)[i * 2]     = lA;
        reinterpret_cast<__nv_bfloat162*>(g_Al)[i * 2 + 1] = lB;
    }
}

// ---------------- HMMA GEMM: [B|C] = A @ Wcomb, split-bf16 x3, TMA loads ---
// 512 threads, 16 warps in 4x4 grid, warp tile 32x32.
// Epilogue: B half -> fp32 Bout; C half -> fp16 Ch + fp16 Yh=dinv*C.
#define STAGE_BYTES 65536
__global__ __launch_bounds__(512)
void hmma_gemm_kernel(const __grid_constant__ CUtensorMap tmAh,
                      const __grid_constant__ CUtensorMap tmAl,
                      const __grid_constant__ CUtensorMap tmWh,
                      const __grid_constant__ CUtensorMap tmWl,
                      int wyoff,
                      const float* __restrict__ bias,
                      float* __restrict__ Bout, __half* __restrict__ Ch,
                      __half* __restrict__ Yh, const float* __restrict__ dinv,
                      int M)
{
    extern __shared__ char dsm_raw[];
    __shared__ __align__(8) unsigned long long s_mbar[2];
    uint32_t dynu = smem_u32(dsm_raw);
    uint32_t pad = ((dynu + 1023) & ~1023u) - dynu;
    uint32_t sb = dynu + pad;
    const uint32_t OFF_AH = 0, OFF_AL = 16384, OFF_BH = 32768, OFF_BL = 49152;

    int tid  = threadIdx.x;
    int warp = tid >> 5, lane = tid & 31;
    int brow = blockIdx.x * 128;
    int ncb  = blockIdx.y * 128;
    int wm   = (warp >> 2) * 32;
    int wn   = (warp & 3) * 32;

    uint32_t mb0 = smem_u32(&s_mbar[0]);
    uint32_t mb1 = smem_u32(&s_mbar[1]);
    if (tid == 0) { MBAR_INIT(mb0, 1); MBAR_INIT(mb1, 1); }
    __syncthreads();

    float acc[2][4][4];
    #pragma unroll
    for (int mi = 0; mi < 2; mi++)
        #pragma unroll
        for (int ni = 0; ni < 4; ni++)
            #pragma unroll
            for (int q = 0; q < 4; q++) acc[mi][ni][q] = 0.0f;

    auto load_chunk = [&](int chunk, int stage) {
        int k0 = chunk * 64;
        uint32_t sbase = sb + stage * STAGE_BYTES;
        uint32_t mb = stage ? mb1 : mb0;
        MBAR_EXPECT_TX(mb, (uint32_t)STAGE_BYTES);
        tma2d(sbase + OFF_AH, &tmAh, k0, brow, mb);
        tma2d(sbase + OFF_AL, &tmAl, k0, brow, mb);
        tma2d(sbase + OFF_BH, &tmWh, k0, wyoff + ncb, mb);
        tma2d(sbase + OFF_BL, &tmWl, k0, wyoff + ncb, mb);
    };

    if (tid == 0) load_chunk(0, 0);

    for (int chunk = 0; chunk < 4; chunk++) {
        int stage = chunk & 1;
        if (chunk < 3 && tid == 0) load_chunk(chunk + 1, stage ^ 1);
        MBAR_WAIT(stage ? mb1 : mb0, (chunk >> 1) & 1);

        uint32_t sbase = sb + stage * STAGE_BYTES;
        #pragma unroll
        for (int ks = 0; ks < 4; ks++) {
            uint32_t kb   = (uint32_t)(ks * 32 + ((lane >> 4) & 1) * 16);
            uint32_t kswz = kb ^ ((uint32_t)(lane & 7) << 4);
            uint32_t rsub = (uint32_t)((lane & 7) + ((lane >> 3) & 1) * 8);

            uint32_t adA = sbase + (wm + rsub) * 128 + kswz;
            uint32_t adB = sbase + (wn + rsub) * 128 + kswz;

            uint32_t a[2][4];                    // reused: hi then lo
            uint32_t bh[2][4], bl[2][4];
            #pragma unroll
            for (int mi = 0; mi < 2; mi++)
                ldsm_x4(a[mi], adA + OFF_AH + mi * 2048);
            #pragma unroll
            for (int nj = 0; nj < 2; nj++) {
                ldsm_x4(bh[nj], adB + OFF_BH + nj * 2048);
                ldsm_x4(bl[nj], adB + OFF_BL + nj * 2048);
            }
            #pragma unroll
            for (int mi = 0; mi < 2; mi++)
                #pragma unroll
                for (int ni = 0; ni < 4; ni++) {
                    int nj = ni >> 1, sel = ni & 1;
                    mma_bf16(acc[mi][ni], a[mi], bh[nj][sel], bh[nj][sel + 2]);
                    mma_bf16(acc[mi][ni], a[mi], bl[nj][sel], bl[nj][sel + 2]);
                }
            #pragma unroll
            for (int mi = 0; mi < 2; mi++)
                ldsm_x4(a[mi], adA + OFF_AL + mi * 2048);
            #pragma unroll
            for (int mi = 0; mi < 2; mi++)
                #pragma unroll
                for (int ni = 0; ni < 4; ni++) {
                    int nj = ni >> 1, sel = ni & 1;
                    mma_bf16(acc[mi][ni], a[mi], bh[nj][sel], bh[nj][sel + 2]);
                }
        }
        __syncthreads();
    }

    bool chalf = (ncb >= 256);
    int  cbase = chalf ? (ncb - 256) : ncb;
    #pragma unroll
    for (int mi = 0; mi < 2; mi++) {
        int row0 = brow + wm + mi * 16 + (lane >> 2);
        int row1 = row0 + 8;
        #pragma unroll
        for (int ni = 0; ni < 4; ni++) {
            int gcol = cbase + wn + ni * 8 + (lane & 3) * 2;
            float2 bb = *(const float2*)(bias + (chalf ? 256 : 0) + gcol);
            float2 v0, v1;
            v0.x = acc[mi][ni][0] + bb.x; v0.y = acc[mi][ni][1] + bb.y;
            v1.x = acc[mi][ni][2] + bb.x; v1.y = acc[mi][ni][3] + bb.y;
            if (!chalf) {
                if (row0 < M) *(float2*)(Bout + (size_t)row0 * 256 + gcol) = v0;
                if (row1 < M) *(float2*)(Bout + (size_t)row1 * 256 + gcol) = v1;
            } else {
                if (row0 < M) {
                    float di = dinv[row0];
                    *(__half2*)(Ch + (size_t)row0 * 256 + gcol) =
                        __floats2half2_rn(v0.x, v0.y);
                    *(__half2*)(Yh + (size_t)row0 * 256 + gcol) =
                        __floats2half2_rn(di * v0.x, di * v0.y);
                }
                if (row1 < M) {
                    float di = dinv[row1];
                    *(__half2*)(Ch + (size_t)row1 * 256 + gcol) =
                        __floats2half2_rn(v1.x, v1.y);
                    *(__half2*)(Yh + (size_t)row1 * 256 + gcol) =
                        __floats2half2_rn(di * v1.x, di * v1.y);
                }
            }
        }
    }
}

// ---------------- fused aggregate + mix + l2norm + relu -> bf16 hi/lo ------
__global__ __launch_bounds__(256)
void agg_combine_kernel(const float* __restrict__ Bm, const __half* __restrict__ Ch,
                        const __half* __restrict__ Yh, int M)
{
    int i = blockIdx.x;
    int t = threadIdx.x;
    if (i >= M) return;

    int g = t >> 5;          // warp 0..7 = neighbor group
    int sl = t & 31;         // lane = feature chunk (8 halves)

    __shared__ int cols[256];
    __shared__ float sacc[8][256];
    __shared__ float wsum[8];

    int s = g_rowstart[i];
    int e = s + g_cnt[i];

    float facc[8];
    #pragma unroll
    for (int q = 0; q < 8; q++) facc[q] = 0.0f;

    for (int base = s; base < e; base += 256) {
        int m = min(256, e - base);
        if (t < m) cols[t] = g_colidx[base + t];
        __syncthreads();
        for (int j = g; j < m; j += 8) {
            const __half* yrow = Yh + (size_t)cols[j] * D_DIM + sl * 8;
            uint4 v = *reinterpret_cast<const uint4*>(yrow);
            const __half2* hp = reinterpret_cast<const __half2*>(&v);
            #pragma unroll
            for (int q = 0; q < 4; q++) {
                float2 f = __half22float2(hp[q]);
                facc[q * 2]     += f.x;
                facc[q * 2 + 1] += f.y;
            }
        }
        __syncthreads();
    }
    #pragma unroll
    for (int q = 0; q < 8; q++) sacc[g][sl * 8 + q] = facc[q];
    __syncthreads();

    float acc = 0.0f;
    #pragma unroll
    for (int g2 = 0; g2 < 8; g2++) acc += sacc[g2][t];

    float di = g_dinv[i];
    float nb = __half2float(Ch[(size_t)i * D_DIM + t]);
    float prop = di * acc + di * di * nb;
    float h = Bm[(size_t)i * D_DIM + t] + 0.5f * prop + 0.5f * nb;

    float v = h * h;
    #pragma unroll
    for (int o = 16; o > 0; o >>= 1)
        v += __shfl_xor_sync(0xffffffffu, v, o);
    if ((t & 31) == 0) wsum[t >> 5] = v;
    __syncthreads();
    float tot = 0.0f;
    #pragma unroll
    for (int w = 0; w < 8; w++) tot += wsum[w];
    float nrm = sqrtf(tot);
    h = fmaxf(h / fmaxf(nrm, 1e-12f), 0.0f);

    __nv_bfloat16 hi = __float2bfloat16(h);
    size_t off = (size_t)i * D_DIM + t;
    g_Ah[off] = hi;
    g_Al[off] = __float2bfloat16(h - __bfloat162float(hi));
}

// ---------------- output GEMM: Out[M,32] = (Hh+Hl) @ W2 + b2 ---------------
__global__ __launch_bounds__(256)
void gemm_out_kernel(const float* __restrict__ W2,
                     const float* __restrict__ b2, float* __restrict__ Out, int M)
{
    extern __shared__ __align__(16) float smem[];
    float* sW = smem;                 // [256][32] (32KB)
    float* sH = smem + D_DIM * 32;    // [64][256] (64KB)

    int tid  = threadIdx.x;
    int brow = blockIdx.x * 64;

    #pragma unroll
    for (int l = 0; l < 8; l++) {
        int idx = tid + l * 256;
        reinterpret_cast<float4*>(sW)[idx] = reinterpret_cast<const float4*>(W2)[idx];
    }
    #pragma unroll
    for (int l = 0; l < 32; l++) {
        int idx = tid + l * 256;       // bf16x2 index into 64x256 (8192 total)
        int r = idx >> 7, c2 = idx & 127;
        float2 f = make_float2(0.f, 0.f);
        if (brow + r < M) {
            size_t off = (size_t)(brow + r) * D_DIM + c2 * 2;
            __nv_bfloat162 hv = *(const __nv_bfloat162*)(g_Ah + off);
            __nv_bfloat162 lv = *(const __nv_bfloat162*)(g_Al + off);
            f.x = __bfloat162float(hv.x) + __bfloat162float(lv.x);
            f.y = __bfloat162float(hv.y) + __bfloat162float(lv.y);
        }
        *reinterpret_cast<float2*>(sH + r * D_DIM + c2 * 2) = f;
    }
    __syncthreads();

    int ry = tid >> 3;            // 0..31; handles rows ry and ry+32
    int c4 = (tid & 7) * 4;
    float4 acc0 = make_float4(0.f, 0.f, 0.f, 0.f);
    float4 acc1 = make_float4(0.f, 0.f, 0.f, 0.f);
    #pragma unroll 8
    for (int k = 0; k < D_DIM; k++) {
        float4 w = *reinterpret_cast<const float4*>(&sW[k * 32 + c4]);
        float h0 = sH[ry * D_DIM + k];
        float h1 = sH[(ry + 32) * D_DIM + k];
        acc0.x = fmaf(h0, w.x, acc0.x); acc0.y = fmaf(h0, w.y, acc0.y);
        acc0.z = fmaf(h0, w.z, acc0.z); acc0.w = fmaf(h0, w.w, acc0.w);
        acc1.x = fmaf(h1, w.x, acc1.x); acc1.y = fmaf(h1, w.y, acc1.y);
        acc1.z = fmaf(h1, w.z, acc1.z); acc1.w = fmaf(h1, w.w, acc1.w);
    }
    float4 bb = *reinterpret_cast<const float4*>(b2 + c4);
    int grow0 = brow + ry, grow1 = brow + ry + 32;
    if (grow0 < M) {
        float4 o; o.x = acc0.x + bb.x; o.y = acc0.y + bb.y;
        o.z = acc0.z + bb.z; o.w = acc0.w + bb.w;
        *reinterpret_cast<float4*>(Out + (size_t)grow0 * O_DIM + c4) = o;
    }
    if (grow1 < M) {
        float4 o; o.x = acc1.x + bb.x; o.y = acc1.y + bb.y;
        o.z = acc1.z + bb.z; o.w = acc1.w + bb.w;
        *reinterpret_cast<float4*>(Out + (size_t)grow1 * O_DIM + c4) = o;
    }
}

// ---------------- host launcher (single stream) ----------------------------
typedef CUresult (CUDAAPI *PFN_encTiled)(
    CUtensorMap*, CUtensorMapDataType, cuuint32_t, void*,
    const cuuint64_t*, const cuuint64_t*, const cuuint32_t*, const cuuint32_t*,
    CUtensorMapInterleave, CUtensorMapSwizzle, CUtensorMapL2promotion,
    CUtensorMapFloatOOBfill);

extern "C" void kernel_launch(void* const* d_in, const int* in_sizes, int n_in,
                              void* d_out, int out_size)
{
    const float* x   = (const float*)d_in[0];
    const int*   ei  = (const int*)  d_in[1];
    const float* W0  = (const float*)d_in[2];
    const float* b0  = (const float*)d_in[3];
    const float* Wn0 = (const float*)d_in[4];
    const float* bn0 = (const float*)d_in[5];
    const float* W1  = (const float*)d_in[6];
    const float* b1  = (const float*)d_in[7];
    const float* Wn1 = (const float*)d_in[8];
    const float* bn1 = (const float*)d_in[9];
    const float* W2  = (const float*)d_in[10];
    const float* b2  = (const float*)d_in[11];

    int M = in_sizes[0] / D_DIM;
    int E = in_sizes[1] / 2;
    const int* erow = ei;
    const int* ecol = ei + E;

    float *pB, *pBiasC, *pDinv;
    __half *pCh, *pYh;
    __nv_bfloat16 *pAh, *pAl, *pWh, *pWl;
    int *pCnt, *pBase;
    cudaGetSymbolAddress((void**)&pB,    g_B);
    cudaGetSymbolAddress((void**)&pCh,   g_Ch);
    cudaGetSymbolAddress((void**)&pYh,   g_Yh);
    cudaGetSymbolAddress((void**)&pDinv, g_dinv);
    cudaGetSymbolAddress((void**)&pAh,   g_Ah);
    cudaGetSymbolAddress((void**)&pAl,   g_Al);
    cudaGetSymbolAddress((void**)&pWh,   g_Wh);
    cudaGetSymbolAddress((void**)&pWl,   g_Wl);
    cudaGetSymbolAddress((void**)&pBiasC, g_biasC);
    cudaGetSymbolAddress((void**)&pCnt,  g_cnt);
    cudaGetSymbolAddress((void**)&pBase, g_base);

    static CUtensorMap tmAh, tmAl, tmWh, tmWl;
    static bool init_done = false;
    if (!init_done) {
        cudaFuncSetAttribute(hmma_gemm_kernel,
                             cudaFuncAttributeMaxDynamicSharedMemorySize,
                             2 * STAGE_BYTES + 1024);
        cudaFuncSetAttribute(gemm_out_kernel,
                             cudaFuncAttributeMaxDynamicSharedMemorySize, 98304);

        void* fp = nullptr;
        cudaDriverEntryPointQueryResult qr;
#if CUDART_VERSION >= 12050
        cudaGetDriverEntryPointByVersion("cuTensorMapEncodeTiled", &fp, 12000,
                                         cudaEnableDefault, &qr);
#else
        cudaGetDriverEntryPoint("cuTensorMapEncodeTiled", &fp,
                                cudaEnableDefault, &qr);
#endif
        PFN_encTiled enc = (PFN_encTiled)fp;

        cuuint64_t dimsA[2] = {256, (cuuint64_t)M};
        cuuint64_t strA[1]  = {256 * 2};
        cuuint64_t dimsW[2] = {256, 1024};
        cuuint64_t strW[1]  = {256 * 2};
        cuuint32_t box[2]   = {64, 128};
        cuuint32_t estr[2]  = {1, 1};
        enc(&tmAh, CU_TENSOR_MAP_DATA_TYPE_BFLOAT16, 2, pAh, dimsA, strA, box,
            estr, CU_TENSOR_MAP_INTERLEAVE_NONE, CU_TENSOR_MAP_SWIZZLE_128B,
            CU_TENSOR_MAP_L2_PROMOTION_L2_128B, CU_TENSOR_MAP_FLOAT_OOB_FILL_NONE);
        enc(&tmAl, CU_TENSOR_MAP_DATA_TYPE_BFLOAT16, 2, pAl, dimsA, strA, box,
            estr, CU_TENSOR_MAP_INTERLEAVE_NONE, CU_TENSOR_MAP_SWIZZLE_128B,
            CU_TENSOR_MAP_L2_PROMOTION_L2_128B, CU_TENSOR_MAP_FLOAT_OOB_FILL_NONE);
        enc(&tmWh, CU_TENSOR_MAP_DATA_TYPE_BFLOAT16, 2, pWh, dimsW, strW, box,
            estr, CU_TENSOR_MAP_INTERLEAVE_NONE, CU_TENSOR_MAP_SWIZZLE_128B,
            CU_TENSOR_MAP_L2_PROMOTION_L2_128B, CU_TENSOR_MAP_FLOAT_OOB_FILL_NONE);
        enc(&tmWl, CU_TENSOR_MAP_DATA_TYPE_BFLOAT16, 2, pWl, dimsW, strW, box,
            estr, CU_TENSOR_MAP_INTERLEAVE_NONE, CU_TENSOR_MAP_SWIZZLE_128B,
            CU_TENSOR_MAP_L2_PROMOTION_L2_128B, CU_TENSOR_MAP_FLOAT_OOB_FILL_NONE);
        init_done = true;
    }

    int eb = (E + 255) / 256;
    int nb = (M + 255) / 256;
    dim3 gg((M + 127) / 128, 4);
    dim3 wfgrid(8, 8, 4), wfblk(32, 8);
    dim3 pgrid(8, 16, 2), pblk(32, 8);

    // CSR build + dinv (before GEMM: its epilogue reads dinv)
    cudaMemsetAsync(pCnt, 0, (size_t)M * sizeof(int));
    cudaMemsetAsync(pBase, 0, sizeof(int));
    count_edges_kernel<<<eb, 256>>>(erow, E);
    offsets_kernel<<<nb, 256>>>(M);
    fill_csr_kernel<<<eb, 256>>>(erow, ecol, E);

    // weight prep (both layers)
    fuse_wf_kernel<<<wfgrid, wfblk>>>(W0, Wn0, W1, Wn1);
    fuse_b_kernel<<<2, 256>>>(b0, Wn0, bn0, b1, Wn1, bn1);
    pack_w_kernel<<<pgrid, pblk>>>(W0, b0, W1, b1);

    // split input
    split_kernel<<<(M * D_DIM / 4 + 255) / 256, 256>>>(x, M * D_DIM / 4);

    // layer 1
    hmma_gemm_kernel<<<gg, 512, 2 * STAGE_BYTES + 1024>>>(
        tmAh, tmAl, tmWh, tmWl, 0, pBiasC, pB, pCh, pYh, pDinv, M);
    agg_combine_kernel<<<M, 256>>>(pB, pCh, pYh, M);

    // layer 2
    hmma_gemm_kernel<<<gg, 512, 2 * STAGE_BYTES + 1024>>>(
        tmAh, tmAl, tmWh, tmWl, 512, pBiasC + 512, pB, pCh, pYh, pDinv, M);
    agg_combine_kernel<<<M, 256>>>(pB, pCh, pYh, M);

    // output layer
    gemm_out_kernel<<<(M + 63) / 64, 256, 98304>>>(W2, b2, (float*)d_out, M);
}